// round 6
// baseline (speedup 1.0000x reference)
#include <cuda_runtime.h>
#include <cuda_bf16.h>
#include <stdint.h>

// LocalitySelfAttention: B=8, N=2304 (48x48), C=512, H=8, D=64.
// bf16x3 error-split MMA; pre-split bf16 hi/lo operands; 2-stage cp.async;
// ldmatrix fragments; register-resident P; flash warp q-tile = 32 rows
// (two 16-row sub-tiles share every K/V fragment load).

constexpr int BB = 8;
constexpr int NN = 2304;
constexpr int CC = 512;
constexpr int HH = 8;
constexpr int DD = 64;
constexpr int GG = 48;
constexpr int M_TOT = BB * NN;          // 18432
constexpr size_t SX  = (size_t)M_TOT * CC;   // 9437184 (= BB*HH*NN*DD)
constexpr size_t SQW = (size_t)1536 * 512;
constexpr size_t SPW = (size_t)512 * 512;
constexpr float LOG2E = 1.4426950408889634f;

__device__ __nv_bfloat16 g_xh[SX],  g_xl[SX];
__device__ __nv_bfloat16 g_wqh[SQW], g_wql[SQW];
__device__ __nv_bfloat16 g_wph[SPW], g_wpl[SPW];
__device__ __nv_bfloat16 g_qh[SX],  g_ql[SX];   // [bh][n][d]
__device__ __nv_bfloat16 g_kh[SX],  g_kl[SX];   // [bh][n][d]
__device__ __nv_bfloat16 g_vth[SX], g_vtl[SX];  // [bh][d][n] (pre-transposed)
__device__ __nv_bfloat16 g_ath[SX], g_atl[SX];  // [b][n][C]
__device__ float4 g_loc[NN];                    // (ky, kx, ky^2+kx^2, 0)

__device__ __forceinline__ uint32_t pack2(__nv_bfloat16 a, __nv_bfloat16 b) {
    __nv_bfloat162 t; t.x = a; t.y = b;
    return *reinterpret_cast<uint32_t*>(&t);
}
__device__ __forceinline__ void split2(float x, __nv_bfloat16& h, __nv_bfloat16& l) {
    h = __float2bfloat16(x);
    l = __float2bfloat16(x - __bfloat162float(h));
}
__device__ __forceinline__ void mma16816(float* c, const uint32_t* a, const uint32_t* b) {
    asm volatile(
        "mma.sync.aligned.m16n8k16.row.col.f32.bf16.bf16.f32 "
        "{%0,%1,%2,%3}, {%4,%5,%6,%7}, {%8,%9}, {%0,%1,%2,%3};"
        : "+f"(c[0]), "+f"(c[1]), "+f"(c[2]), "+f"(c[3])
        : "r"(a[0]), "r"(a[1]), "r"(a[2]), "r"(a[3]), "r"(b[0]), "r"(b[1]));
}
__device__ __forceinline__ void ldsm_x4(uint32_t* r, uint32_t addr) {
    asm volatile("ldmatrix.sync.aligned.m8n8.x4.shared.b16 {%0,%1,%2,%3}, [%4];"
        : "=r"(r[0]), "=r"(r[1]), "=r"(r[2]), "=r"(r[3]) : "r"(addr));
}
__device__ __forceinline__ uint32_t s2u(const void* p) {
    return (uint32_t)__cvta_generic_to_shared(p);
}
__device__ __forceinline__ void cpa16(uint32_t s, const void* g) {
    asm volatile("cp.async.ca.shared.global [%0], [%1], 16;" :: "r"(s), "l"(g));
}
#define CP_COMMIT() asm volatile("cp.async.commit_group;")
#define CP_WAIT0()  asm volatile("cp.async.wait_group 0;")
#define CP_WAIT1()  asm volatile("cp.async.wait_group 1;")

// ---------------------------------------------------------------------------
// Prep: split fp32 inputs into bf16 hi/lo + locality LUT.
// ---------------------------------------------------------------------------
__global__ __launch_bounds__(256)
void prep_split(const float* __restrict__ x, const float* __restrict__ wq,
                const float* __restrict__ wp) {
    const size_t gid = (size_t)blockIdx.x * 256 + threadIdx.x;
    if (gid < NN) {
        const int y = (int)(gid / GG), xx = (int)(gid - (size_t)y * GG);
        const float fy = (float)y, fx = (float)xx;
        g_loc[gid] = make_float4(fy, fx, fy * fy + fx * fx, 0.0f);
    }
    const size_t i4 = gid * 4;
    const float* src; __nv_bfloat16 *dh, *dl; size_t off;
    if (i4 < SX)                  { src = x;  dh = g_xh;  dl = g_xl;  off = i4; }
    else if (i4 < SX + SQW)       { src = wq; dh = g_wqh; dl = g_wql; off = i4 - SX; }
    else if (i4 < SX + SQW + SPW) { src = wp; dh = g_wph; dl = g_wpl; off = i4 - SX - SQW; }
    else return;
    const float4 v = *(const float4*)(src + off);
    __nv_bfloat16 h0, l0, h1, l1, h2, l2, h3, l3;
    split2(v.x, h0, l0); split2(v.y, h1, l1);
    split2(v.z, h2, l2); split2(v.w, h3, l3);
    *(uint32_t*)&dh[off]     = pack2(h0, h1);
    *(uint32_t*)&dh[off + 2] = pack2(h2, h3);
    *(uint32_t*)&dl[off]     = pack2(l0, l1);
    *(uint32_t*)&dl[off + 2] = pack2(l2, l3);
}

// ---------------------------------------------------------------------------
// GEMM: block 128x128, k-chunk 32, 8 warps (2m x 4n), 2-stage cp.async pipe.
// ---------------------------------------------------------------------------
constexpr int GSTR = 40;
constexpr int G_TILE = 128 * GSTR;
constexpr int G_STAGE = 4 * G_TILE;
constexpr int G_SMEM = 2 * G_STAGE * 2;

template <int MODE>
__global__ __launch_bounds__(256, 2)
void mma_gemm(const float* __restrict__ bias, float* __restrict__ out) {
    extern __shared__ __nv_bfloat16 smem[];

    const __nv_bfloat16* Ah = (MODE == 0) ? g_xh : g_ath;
    const __nv_bfloat16* Al = (MODE == 0) ? g_xl : g_atl;
    const __nv_bfloat16* Bh = (MODE == 0) ? g_wqh : g_wph;
    const __nv_bfloat16* Bl = (MODE == 0) ? g_wql : g_wpl;

    const int tid = threadIdx.x;
    const int lane = tid & 31, warp = tid >> 5;
    const int wm = warp >> 2, wn = warp & 3;
    const int bm = blockIdx.x * 128, bn = blockIdx.y * 128;

    auto load_stage = [&](int s, int k0) {
        __nv_bfloat16* base = smem + s * G_STAGE;
#pragma unroll
        for (int it = 0; it < 2; it++) {
            const int c = tid + 256 * it;
            const int row = c >> 2, col = c & 3;
            const size_t ga = (size_t)(bm + row) * CC + k0 + col * 8;
            const size_t gb = (size_t)(bn + row) * CC + k0 + col * 8;
            const int so = row * GSTR + col * 8;
            cpa16(s2u(base + so), &Ah[ga]);
            cpa16(s2u(base + G_TILE + so), &Al[ga]);
            cpa16(s2u(base + 2 * G_TILE + so), &Bh[gb]);
            cpa16(s2u(base + 3 * G_TILE + so), &Bl[gb]);
        }
        CP_COMMIT();
    };

    float acc[4][4][4];
#pragma unroll
    for (int i = 0; i < 4; i++)
#pragma unroll
        for (int j = 0; j < 4; j++)
#pragma unroll
            for (int r = 0; r < 4; r++) acc[i][j][r] = 0.0f;

    constexpr int NIT = CC / 32;
    load_stage(0, 0);
    for (int i = 0; i < NIT; i++) {
        if (i + 1 < NIT) { load_stage((i + 1) & 1, (i + 1) * 32); CP_WAIT1(); }
        else             { CP_WAIT0(); }
        __syncthreads();
        const __nv_bfloat16* sAh = smem + (i & 1) * G_STAGE;
        const __nv_bfloat16* sAl = sAh + G_TILE;
        const __nv_bfloat16* sBh = sAh + 2 * G_TILE;
        const __nv_bfloat16* sBl = sAh + 3 * G_TILE;

        uint32_t bh_[4][4], bl_[4][4];
#pragma unroll
        for (int nt = 0; nt < 4; nt++) {
            const int boff = (wn * 32 + nt * 8 + (lane & 7)) * GSTR + (lane >> 3) * 8;
            ldsm_x4(bh_[nt], s2u(&sBh[boff]));
            ldsm_x4(bl_[nt], s2u(&sBl[boff]));
        }
#pragma unroll
        for (int mt = 0; mt < 4; mt++) {
            uint32_t ah[2][4], al[2][4];
#pragma unroll
            for (int s = 0; s < 2; s++) {
                const int aoff = (wm * 64 + mt * 16 + (lane & 15)) * GSTR + s * 16 + (lane >> 4) * 8;
                ldsm_x4(ah[s], s2u(&sAh[aoff]));
                ldsm_x4(al[s], s2u(&sAl[aoff]));
            }
#pragma unroll
            for (int s = 0; s < 2; s++)
#pragma unroll
                for (int nt = 0; nt < 4; nt++) {
                    mma16816(acc[mt][nt], ah[s], &bh_[nt][2 * s]);
                    mma16816(acc[mt][nt], ah[s], &bl_[nt][2 * s]);
                    mma16816(acc[mt][nt], al[s], &bh_[nt][2 * s]);
                }
        }
        __syncthreads();
    }

#pragma unroll
    for (int mt = 0; mt < 4; mt++) {
#pragma unroll
        for (int nt = 0; nt < 4; nt++) {
            const int rA = bm + wm * 64 + mt * 16 + (lane >> 2);
            const int rB = rA + 8;
            const int o = bn + wn * 32 + nt * 8 + 2 * (lane & 3);
            if (MODE == 0) {
                const int part = o >> 9, h = (o >> 6) & 7, d = o & 63;
                const int bA = rA / NN, nA = rA - bA * NN;
                const int bB = rB / NN, nB = rB - bB * NN;
                const int bhA = bA * HH + h, bhB = bB * HH + h;
                __nv_bfloat16 h0, l0, h1, l1, h2, l2, h3, l3;
                split2(acc[mt][nt][0], h0, l0); split2(acc[mt][nt][1], h1, l1);
                split2(acc[mt][nt][2], h2, l2); split2(acc[mt][nt][3], h3, l3);
                if (part == 2) {
                    const size_t iA = ((size_t)bhA * DD + d) * NN + nA;
                    const size_t iB = ((size_t)bhB * DD + d) * NN + nB;
                    g_vth[iA] = h0; g_vtl[iA] = l0;
                    g_vth[iA + NN] = h1; g_vtl[iA + NN] = l1;
                    g_vth[iB] = h2; g_vtl[iB] = l2;
                    g_vth[iB + NN] = h3; g_vtl[iB + NN] = l3;
                } else {
                    __nv_bfloat16* dh = (part == 0) ? g_qh : g_kh;
                    __nv_bfloat16* dl = (part == 0) ? g_ql : g_kl;
                    const size_t iA = ((size_t)bhA * NN + nA) * DD + d;
                    const size_t iB = ((size_t)bhB * NN + nB) * DD + d;
                    *(uint32_t*)&dh[iA] = pack2(h0, h1);
                    *(uint32_t*)&dl[iA] = pack2(l0, l1);
                    *(uint32_t*)&dh[iB] = pack2(h2, h3);
                    *(uint32_t*)&dl[iB] = pack2(l2, l3);
                }
            } else {
                const float b0 = bias[o], b1 = bias[o + 1];
                *(float2*)&out[(size_t)rA * CC + o] =
                    make_float2(acc[mt][nt][0] + b0, acc[mt][nt][1] + b1);
                *(float2*)&out[(size_t)rB * CC + o] =
                    make_float2(acc[mt][nt][2] + b0, acc[mt][nt][3] + b1);
            }
        }
    }
}

// ---------------------------------------------------------------------------
// Flash attention. CTA = 256 queries x one (b,h), 8 warps x 32q each (two
// 16-row sub-tiles g=0,1 sharing K/V fragment loads). 64-key tiles, 2-stage
// cp.async. exp2-domain softmax. Q tiles resident in smem, frags in regs.
// ---------------------------------------------------------------------------
constexpr int FSTR = 72;
constexpr int FQ_ELE = 256 * FSTR;       // per Q array (hi or lo)
constexpr int F_TILE = 64 * FSTR;
constexpr int F_STAGE = 4 * F_TILE;      // Kh, Kl, Vh, Vl
constexpr int F_SMEM = (2 * FQ_ELE + 2 * F_STAGE) * 2;  // 147456 B

__global__ __launch_bounds__(256, 1)
void flash_mma(const float* __restrict__ temp, const float* __restrict__ lw) {
    extern __shared__ __nv_bfloat16 smem[];
    __nv_bfloat16* Qsh = smem;
    __nv_bfloat16* Qsl = smem + FQ_ELE;
    __nv_bfloat16* kvs = smem + 2 * FQ_ELE;

    const int tid = threadIdx.x;
    const int lane = tid & 31, warp = tid >> 5;
    const int q0 = blockIdx.x * 256;
    const int bh = blockIdx.y;
    const int h = bh & 7, b = bh >> 3;

    const __nv_bfloat16* Qh = g_qh + (size_t)bh * NN * DD;
    const __nv_bfloat16* Ql = g_ql + (size_t)bh * NN * DD;
    const __nv_bfloat16* Kh = g_kh + (size_t)bh * NN * DD;
    const __nv_bfloat16* Kl = g_kl + (size_t)bh * NN * DD;
    const __nv_bfloat16* Vh = g_vth + (size_t)bh * NN * DD;  // [d][n]
    const __nv_bfloat16* Vl = g_vtl + (size_t)bh * NN * DD;

    const float scale2 = __expf(temp[h]) * LOG2E;   // log2-domain scale
    const float wb2 = lw[h] * (LOG2E / 4418.0f);    // log2-domain bias weight

    // ---- Stage Q (256x64 hi/lo) resident in smem ----
#pragma unroll
    for (int it = 0; it < 8; it++) {
        const int c = tid + 256 * it;          // 2048 chunks per array
        const int row = c >> 3, col = c & 7;
        const size_t g = (size_t)(q0 + row) * DD + col * 8;
        const int so = row * FSTR + col * 8;
        cpa16(s2u(&Qsh[so]), &Qh[g]);
        cpa16(s2u(&Qsl[so]), &Ql[g]);
    }
    CP_COMMIT();
    CP_WAIT0();
    __syncthreads();

    // Q fragments for both sub-tiles, held in registers for whole kernel
    uint32_t qfh[2][4][4], qfl[2][4][4];
#pragma unroll
    for (int g = 0; g < 2; g++)
#pragma unroll
        for (int s = 0; s < 4; s++) {
            const int off = (warp * 32 + g * 16 + (lane & 15)) * FSTR + s * 16 + (lane >> 4) * 8;
            ldsm_x4(qfh[g][s], s2u(&Qsh[off]));
            ldsm_x4(qfl[g][s], s2u(&Qsl[off]));
        }

    auto load_kv = [&](int s, int k0) {
        __nv_bfloat16* base = kvs + s * F_STAGE;
#pragma unroll
        for (int it = 0; it < 2; it++) {
            const int c = tid + 256 * it;
            const int row = c >> 3, col = c & 7;
            const size_t gk = (size_t)(k0 + row) * DD + col * 8;
            const size_t gv = (size_t)row * NN + k0 + col * 8;
            const int so = row * FSTR + col * 8;
            cpa16(s2u(base + so), &Kh[gk]);
            cpa16(s2u(base + F_TILE + so), &Kl[gk]);
            cpa16(s2u(base + 2 * F_TILE + so), &Vh[gv]);
            cpa16(s2u(base + 3 * F_TILE + so), &Vl[gv]);
        }
        CP_COMMIT();
    };

    float oacc[2][8][4];
#pragma unroll
    for (int g = 0; g < 2; g++)
#pragma unroll
        for (int u = 0; u < 8; u++)
#pragma unroll
            for (int r = 0; r < 4; r++) oacc[g][u][r] = 0.0f;
    float mrow[2][2], lsum[2][2];
#pragma unroll
    for (int g = 0; g < 2; g++) {
        mrow[g][0] = mrow[g][1] = -1e30f;
        lsum[g][0] = lsum[g][1] = 0.0f;
    }

    // per-(g, half) locality constants (log2 domain)
    float byc[2][2], bxc[2][2];
#pragma unroll
    for (int g = 0; g < 2; g++)
#pragma unroll
        for (int hf = 0; hf < 2; hf++) {
            const int q = q0 + warp * 32 + g * 16 + (lane >> 2) + hf * 8;
            const float4 ql4 = g_loc[q];
            byc[g][hf] = 2.0f * wb2 * ql4.x;
            bxc[g][hf] = 2.0f * wb2 * ql4.y;
        }

    constexpr int NKT = NN / 64;  // 36
    load_kv(0, 0);
    for (int kt = 0; kt < NKT; kt++) {
        if (kt + 1 < NKT) { load_kv((kt + 1) & 1, (kt + 1) * 64); CP_WAIT1(); }
        else              { CP_WAIT0(); }
        __syncthreads();
        const __nv_bfloat16* sKh = kvs + (kt & 1) * F_STAGE;
        const __nv_bfloat16* sKl = sKh + F_TILE;
        const __nv_bfloat16* sVh = sKh + 2 * F_TILE;
        const __nv_bfloat16* sVl = sKh + 3 * F_TILE;
        const int k0 = kt * 64;

        // S = Q @ K^T : 32 x 64 per warp, K frags shared by both sub-tiles
        float sfr[2][8][4];
#pragma unroll
        for (int g = 0; g < 2; g++)
#pragma unroll
            for (int t = 0; t < 8; t++)
#pragma unroll
                for (int r = 0; r < 4; r++) sfr[g][t][r] = 0.0f;
#pragma unroll
        for (int t = 0; t < 8; t++) {
            const int base = (8 * t + (lane & 7)) * FSTR + (lane >> 3) * 8;
            uint32_t k0h[4], k1h[4], k0l[4], k1l[4];
            ldsm_x4(k0h, s2u(&sKh[base]));
            ldsm_x4(k1h, s2u(&sKh[base + 32]));
            ldsm_x4(k0l, s2u(&sKl[base]));
            ldsm_x4(k1l, s2u(&sKl[base + 32]));
#pragma unroll
            for (int g = 0; g < 2; g++) {
                mma16816(sfr[g][t], qfh[g][0], &k0h[0]); mma16816(sfr[g][t], qfh[g][0], &k0l[0]); mma16816(sfr[g][t], qfl[g][0], &k0h[0]);
                mma16816(sfr[g][t], qfh[g][1], &k0h[2]); mma16816(sfr[g][t], qfh[g][1], &k0l[2]); mma16816(sfr[g][t], qfl[g][1], &k0h[2]);
                mma16816(sfr[g][t], qfh[g][2], &k1h[0]); mma16816(sfr[g][t], qfh[g][2], &k1l[0]); mma16816(sfr[g][t], qfl[g][2], &k1h[0]);
                mma16816(sfr[g][t], qfh[g][3], &k1h[2]); mma16816(sfr[g][t], qfh[g][3], &k1l[2]); mma16816(sfr[g][t], qfl[g][3], &k1h[2]);
            }
        }

        // softmax per sub-tile (log2 domain); pack P frags in registers
        uint32_t ah[2][4][4], al[2][4][4];
#pragma unroll
        for (int g = 0; g < 2; g++) {
            float tmA = -1e30f, tmB = -1e30f;
#pragma unroll
            for (int t = 0; t < 8; t++) {
#pragma unroll
                for (int j = 0; j < 2; j++) {
                    const int k = k0 + 8 * t + 2 * (lane & 3) + j;
                    const float4 kl4 = __ldg(&g_loc[k]);
                    const float cA = fmaf(byc[g][0], kl4.x, fmaf(bxc[g][0], kl4.y, -wb2 * kl4.z));
                    const float cB = fmaf(byc[g][1], kl4.x, fmaf(bxc[g][1], kl4.y, -wb2 * kl4.z));
                    sfr[g][t][j]     = fmaf(sfr[g][t][j],     scale2, cA);
                    sfr[g][t][2 + j] = fmaf(sfr[g][t][2 + j], scale2, cB);
                    tmA = fmaxf(tmA, sfr[g][t][j]);
                    tmB = fmaxf(tmB, sfr[g][t][2 + j]);
                }
            }
            tmA = fmaxf(tmA, __shfl_xor_sync(0xffffffffu, tmA, 1));
            tmA = fmaxf(tmA, __shfl_xor_sync(0xffffffffu, tmA, 2));
            tmB = fmaxf(tmB, __shfl_xor_sync(0xffffffffu, tmB, 1));
            tmB = fmaxf(tmB, __shfl_xor_sync(0xffffffffu, tmB, 2));
            const float mnA = fmaxf(mrow[g][0], tmA), mnB = fmaxf(mrow[g][1], tmB);
            const float facA = exp2f(mrow[g][0] - mnA), facB = exp2f(mrow[g][1] - mnB);
            mrow[g][0] = mnA; mrow[g][1] = mnB;

            float rsA = 0.0f, rsB = 0.0f;
#pragma unroll
            for (int s = 0; s < 4; s++) {
                const float p0 = exp2f(sfr[g][2 * s][0] - mnA);
                const float p1 = exp2f(sfr[g][2 * s][1] - mnA);
                const float p2 = exp2f(sfr[g][2 * s][2] - mnB);
                const float p3 = exp2f(sfr[g][2 * s][3] - mnB);
                const float r0 = exp2f(sfr[g][2 * s + 1][0] - mnA);
                const float r1 = exp2f(sfr[g][2 * s + 1][1] - mnA);
                const float r2 = exp2f(sfr[g][2 * s + 1][2] - mnB);
                const float r3 = exp2f(sfr[g][2 * s + 1][3] - mnB);
                rsA += p0 + p1 + r0 + r1;
                rsB += p2 + p3 + r2 + r3;
                __nv_bfloat16 h0, l0, h1, l1;
                split2(p0, h0, l0); split2(p1, h1, l1);
                ah[g][s][0] = pack2(h0, h1); al[g][s][0] = pack2(l0, l1);
                split2(p2, h0, l0); split2(p3, h1, l1);
                ah[g][s][1] = pack2(h0, h1); al[g][s][1] = pack2(l0, l1);
                split2(r0, h0, l0); split2(r1, h1, l1);
                ah[g][s][2] = pack2(h0, h1); al[g][s][2] = pack2(l0, l1);
                split2(r2, h0, l0); split2(r3, h1, l1);
                ah[g][s][3] = pack2(h0, h1); al[g][s][3] = pack2(l0, l1);
            }
            rsA += __shfl_xor_sync(0xffffffffu, rsA, 1);
            rsA += __shfl_xor_sync(0xffffffffu, rsA, 2);
            rsB += __shfl_xor_sync(0xffffffffu, rsB, 1);
            rsB += __shfl_xor_sync(0xffffffffu, rsB, 2);
            lsum[g][0] = lsum[g][0] * facA + rsA;
            lsum[g][1] = lsum[g][1] * facB + rsB;
#pragma unroll
            for (int u = 0; u < 8; u++) {
                oacc[g][u][0] *= facA; oacc[g][u][1] *= facA;
                oacc[g][u][2] *= facB; oacc[g][u][3] *= facB;
            }
        }

        // O += P @ V : V frags shared by both sub-tiles
#pragma unroll
        for (int u = 0; u < 8; u++) {
            const int base = (8 * u + (lane & 7)) * FSTR + (lane >> 3) * 8;
            uint32_t v0h[4], v1h[4], v0l[4], v1l[4];
            ldsm_x4(v0h, s2u(&sVh[base]));
            ldsm_x4(v1h, s2u(&sVh[base + 32]));
            ldsm_x4(v0l, s2u(&sVl[base]));
            ldsm_x4(v1l, s2u(&sVl[base + 32]));
#pragma unroll
            for (int g = 0; g < 2; g++) {
                mma16816(oacc[g][u], ah[g][0], &v0h[0]); mma16816(oacc[g][u], ah[g][0], &v0l[0]); mma16816(oacc[g][u], al[g][0], &v0h[0]);
                mma16816(oacc[g][u], ah[g][1], &v0h[2]); mma16816(oacc[g][u], ah[g][1], &v0l[2]); mma16816(oacc[g][u], al[g][1], &v0h[2]);
                mma16816(oacc[g][u], ah[g][2], &v1h[0]); mma16816(oacc[g][u], ah[g][2], &v1l[0]); mma16816(oacc[g][u], al[g][2], &v1h[0]);
                mma16816(oacc[g][u], ah[g][3], &v1h[2]); mma16816(oacc[g][u], ah[g][3], &v1l[2]); mma16816(oacc[g][u], al[g][3], &v1h[2]);
            }
        }
        __syncthreads();
    }

    // epilogue: normalize, split, write att bf16 hi/lo [b][n][C]
#pragma unroll
    for (int g = 0; g < 2; g++) {
        const float invA = 1.0f / lsum[g][0], invB = 1.0f / lsum[g][1];
        const int qA = q0 + warp * 32 + g * 16 + (lane >> 2);
        const size_t baseA = ((size_t)(b * NN + qA)) * CC + h * DD;
        const size_t baseB = ((size_t)(b * NN + qA + 8)) * CC + h * DD;
#pragma unroll
        for (int u = 0; u < 8; u++) {
            const int c = 8 * u + 2 * (lane & 3);
            __nv_bfloat16 h0, l0, h1, l1;
            split2(oacc[g][u][0] * invA, h0, l0); split2(oacc[g][u][1] * invA, h1, l1);
            *(uint32_t*)&g_ath[baseA + c] = pack2(h0, h1);
            *(uint32_t*)&g_atl[baseA + c] = pack2(l0, l1);
            split2(oacc[g][u][2] * invB, h0, l0); split2(oacc[g][u][3] * invB, h1, l1);
            *(uint32_t*)&g_ath[baseB + c] = pack2(h0, h1);
            *(uint32_t*)&g_atl[baseB + c] = pack2(l0, l1);
        }
    }
}

// ---------------------------------------------------------------------------
extern "C" void kernel_launch(void* const* d_in, const int* in_sizes, int n_in,
                              void* d_out, int out_size) {
    const float* x      = (const float*)d_in[0];
    const float* qkv_w  = (const float*)d_in[1];
    const float* proj_w = (const float*)d_in[2];
    const float* proj_b = (const float*)d_in[3];
    const float* temp   = (const float*)d_in[4];
    const float* lw     = (const float*)d_in[5];
    float* out = (float*)d_out;

    cudaFuncSetAttribute(mma_gemm<0>, cudaFuncAttributeMaxDynamicSharedMemorySize, G_SMEM);
    cudaFuncSetAttribute(mma_gemm<1>, cudaFuncAttributeMaxDynamicSharedMemorySize, G_SMEM);
    cudaFuncSetAttribute(flash_mma,   cudaFuncAttributeMaxDynamicSharedMemorySize, F_SMEM);

    const int prep_blocks = (int)((SX + SQW + SPW) / 4 / 256);
    prep_split<<<prep_blocks, 256>>>(x, qkv_w, proj_w);

    mma_gemm<0><<<dim3(M_TOT / 128, 1536 / 128), 256, G_SMEM>>>(nullptr, nullptr);

    flash_mma<<<dim3(NN / 256, BB * HH), 256, F_SMEM>>>(temp, lw);

    mma_gemm<1><<<dim3(M_TOT / 128, CC / 128), 256, G_SMEM>>>(proj_b, out);
}

// round 7
// speedup vs baseline: 1.5490x; 1.5490x over previous
#include <cuda_runtime.h>
#include <cuda_bf16.h>
#include <cuda_fp16.h>
#include <stdint.h>

// LocalitySelfAttention: B=8, N=2304 (48x48), C=512, H=8, D=64.
// GEMMs: bf16x3 error-split MMA (fp32-class). Attention: single-pass fp16 MMA
// (err ~4e-4 < 1e-3). cp.async pipelines, ldmatrix frags, register P.

constexpr int BB = 8;
constexpr int NN = 2304;
constexpr int CC = 512;
constexpr int HH = 8;
constexpr int DD = 64;
constexpr int GG = 48;
constexpr int M_TOT = BB * NN;          // 18432
constexpr size_t SX  = (size_t)M_TOT * CC;   // 9437184 (= BB*HH*NN*DD)
constexpr size_t SQW = (size_t)1536 * 512;
constexpr size_t SPW = (size_t)512 * 512;
constexpr float LOG2E = 1.4426950408889634f;

__device__ __nv_bfloat16 g_xh[SX],  g_xl[SX];
__device__ __nv_bfloat16 g_wqh[SQW], g_wql[SQW];
__device__ __nv_bfloat16 g_wph[SPW], g_wpl[SPW];
__device__ __half g_qf[SX];                     // [bh][n][d] fp16
__device__ __half g_kf[SX];                     // [bh][n][d] fp16
__device__ __half g_vtf[SX];                    // [bh][d][n] fp16 (transposed)
__device__ __nv_bfloat16 g_ath[SX], g_atl[SX];  // [b][n][C]
__device__ float4 g_loc[NN];                    // (ky, kx, ky^2+kx^2, 0)

__device__ __forceinline__ uint32_t pack2(__nv_bfloat16 a, __nv_bfloat16 b) {
    __nv_bfloat162 t; t.x = a; t.y = b;
    return *reinterpret_cast<uint32_t*>(&t);
}
__device__ __forceinline__ uint32_t pack2h(__half a, __half b) {
    __half2 t; t.x = a; t.y = b;
    return *reinterpret_cast<uint32_t*>(&t);
}
__device__ __forceinline__ void split2(float x, __nv_bfloat16& h, __nv_bfloat16& l) {
    h = __float2bfloat16(x);
    l = __float2bfloat16(x - __bfloat162float(h));
}
__device__ __forceinline__ void mma16816(float* c, const uint32_t* a, const uint32_t* b) {
    asm volatile(
        "mma.sync.aligned.m16n8k16.row.col.f32.bf16.bf16.f32 "
        "{%0,%1,%2,%3}, {%4,%5,%6,%7}, {%8,%9}, {%0,%1,%2,%3};"
        : "+f"(c[0]), "+f"(c[1]), "+f"(c[2]), "+f"(c[3])
        : "r"(a[0]), "r"(a[1]), "r"(a[2]), "r"(a[3]), "r"(b[0]), "r"(b[1]));
}
__device__ __forceinline__ void mma16816h(float* c, const uint32_t* a, const uint32_t* b) {
    asm volatile(
        "mma.sync.aligned.m16n8k16.row.col.f32.f16.f16.f32 "
        "{%0,%1,%2,%3}, {%4,%5,%6,%7}, {%8,%9}, {%0,%1,%2,%3};"
        : "+f"(c[0]), "+f"(c[1]), "+f"(c[2]), "+f"(c[3])
        : "r"(a[0]), "r"(a[1]), "r"(a[2]), "r"(a[3]), "r"(b[0]), "r"(b[1]));
}
__device__ __forceinline__ void ldsm_x4(uint32_t* r, uint32_t addr) {
    asm volatile("ldmatrix.sync.aligned.m8n8.x4.shared.b16 {%0,%1,%2,%3}, [%4];"
        : "=r"(r[0]), "=r"(r[1]), "=r"(r[2]), "=r"(r[3]) : "r"(addr));
}
__device__ __forceinline__ uint32_t s2u(const void* p) {
    return (uint32_t)__cvta_generic_to_shared(p);
}
__device__ __forceinline__ void cpa16(uint32_t s, const void* g) {
    asm volatile("cp.async.ca.shared.global [%0], [%1], 16;" :: "r"(s), "l"(g));
}
#define CP_COMMIT() asm volatile("cp.async.commit_group;")
#define CP_WAIT0()  asm volatile("cp.async.wait_group 0;")
#define CP_WAIT1()  asm volatile("cp.async.wait_group 1;")

// ---------------------------------------------------------------------------
// Prep: split fp32 inputs into bf16 hi/lo + locality LUT.
// ---------------------------------------------------------------------------
__global__ __launch_bounds__(256)
void prep_split(const float* __restrict__ x, const float* __restrict__ wq,
                const float* __restrict__ wp) {
    const size_t gid = (size_t)blockIdx.x * 256 + threadIdx.x;
    if (gid < NN) {
        const int y = (int)(gid / GG), xx = (int)(gid - (size_t)y * GG);
        const float fy = (float)y, fx = (float)xx;
        g_loc[gid] = make_float4(fy, fx, fy * fy + fx * fx, 0.0f);
    }
    const size_t i4 = gid * 4;
    const float* src; __nv_bfloat16 *dh, *dl; size_t off;
    if (i4 < SX)                  { src = x;  dh = g_xh;  dl = g_xl;  off = i4; }
    else if (i4 < SX + SQW)       { src = wq; dh = g_wqh; dl = g_wql; off = i4 - SX; }
    else if (i4 < SX + SQW + SPW) { src = wp; dh = g_wph; dl = g_wpl; off = i4 - SX - SQW; }
    else return;
    const float4 v = *(const float4*)(src + off);
    __nv_bfloat16 h0, l0, h1, l1, h2, l2, h3, l3;
    split2(v.x, h0, l0); split2(v.y, h1, l1);
    split2(v.z, h2, l2); split2(v.w, h3, l3);
    *(uint32_t*)&dh[off]     = pack2(h0, h1);
    *(uint32_t*)&dh[off + 2] = pack2(h2, h3);
    *(uint32_t*)&dl[off]     = pack2(l0, l1);
    *(uint32_t*)&dl[off + 2] = pack2(l2, l3);
}

// ---------------------------------------------------------------------------
// GEMM: block 128x128, k-chunk 32, 8 warps (2m x 4n), 2-stage cp.async pipe.
// MODE 0: x @ Wqkv^T -> q/k fp16 [bh][n][d], v fp16 transposed [bh][d][n].
// MODE 1: att @ Wproj^T + bias -> fp32 out.
// ---------------------------------------------------------------------------
constexpr int GSTR = 40;
constexpr int G_TILE = 128 * GSTR;
constexpr int G_STAGE = 4 * G_TILE;
constexpr int G_SMEM = 2 * G_STAGE * 2;

template <int MODE>
__global__ __launch_bounds__(256, 2)
void mma_gemm(const float* __restrict__ bias, float* __restrict__ out) {
    extern __shared__ __nv_bfloat16 smem[];

    const __nv_bfloat16* Ah = (MODE == 0) ? g_xh : g_ath;
    const __nv_bfloat16* Al = (MODE == 0) ? g_xl : g_atl;
    const __nv_bfloat16* Bh = (MODE == 0) ? g_wqh : g_wph;
    const __nv_bfloat16* Bl = (MODE == 0) ? g_wql : g_wpl;

    const int tid = threadIdx.x;
    const int lane = tid & 31, warp = tid >> 5;
    const int wm = warp >> 2, wn = warp & 3;
    const int bm = blockIdx.x * 128, bn = blockIdx.y * 128;

    auto load_stage = [&](int s, int k0) {
        __nv_bfloat16* base = smem + s * G_STAGE;
#pragma unroll
        for (int it = 0; it < 2; it++) {
            const int c = tid + 256 * it;
            const int row = c >> 2, col = c & 3;
            const size_t ga = (size_t)(bm + row) * CC + k0 + col * 8;
            const size_t gb = (size_t)(bn + row) * CC + k0 + col * 8;
            const int so = row * GSTR + col * 8;
            cpa16(s2u(base + so), &Ah[ga]);
            cpa16(s2u(base + G_TILE + so), &Al[ga]);
            cpa16(s2u(base + 2 * G_TILE + so), &Bh[gb]);
            cpa16(s2u(base + 3 * G_TILE + so), &Bl[gb]);
        }
        CP_COMMIT();
    };

    float acc[4][4][4];
#pragma unroll
    for (int i = 0; i < 4; i++)
#pragma unroll
        for (int j = 0; j < 4; j++)
#pragma unroll
            for (int r = 0; r < 4; r++) acc[i][j][r] = 0.0f;

    constexpr int NIT = CC / 32;
    load_stage(0, 0);
    for (int i = 0; i < NIT; i++) {
        if (i + 1 < NIT) { load_stage((i + 1) & 1, (i + 1) * 32); CP_WAIT1(); }
        else             { CP_WAIT0(); }
        __syncthreads();
        const __nv_bfloat16* sAh = smem + (i & 1) * G_STAGE;
        const __nv_bfloat16* sAl = sAh + G_TILE;
        const __nv_bfloat16* sBh = sAh + 2 * G_TILE;
        const __nv_bfloat16* sBl = sAh + 3 * G_TILE;

        uint32_t bh_[4][4], bl_[4][4];
#pragma unroll
        for (int nt = 0; nt < 4; nt++) {
            const int boff = (wn * 32 + nt * 8 + (lane & 7)) * GSTR + (lane >> 3) * 8;
            ldsm_x4(bh_[nt], s2u(&sBh[boff]));
            ldsm_x4(bl_[nt], s2u(&sBl[boff]));
        }
#pragma unroll
        for (int mt = 0; mt < 4; mt++) {
            uint32_t ah[2][4], al[2][4];
#pragma unroll
            for (int s = 0; s < 2; s++) {
                const int aoff = (wm * 64 + mt * 16 + (lane & 15)) * GSTR + s * 16 + (lane >> 4) * 8;
                ldsm_x4(ah[s], s2u(&sAh[aoff]));
                ldsm_x4(al[s], s2u(&sAl[aoff]));
            }
#pragma unroll
            for (int s = 0; s < 2; s++)
#pragma unroll
                for (int nt = 0; nt < 4; nt++) {
                    mma16816(acc[mt][nt], ah[s], &bh_[nt][2 * s]);
                    mma16816(acc[mt][nt], ah[s], &bl_[nt][2 * s]);
                    mma16816(acc[mt][nt], al[s], &bh_[nt][2 * s]);
                }
        }
        __syncthreads();
    }

#pragma unroll
    for (int mt = 0; mt < 4; mt++) {
#pragma unroll
        for (int nt = 0; nt < 4; nt++) {
            const int rA = bm + wm * 64 + mt * 16 + (lane >> 2);
            const int rB = rA + 8;
            const int o = bn + wn * 32 + nt * 8 + 2 * (lane & 3);
            if (MODE == 0) {
                const int part = o >> 9, h = (o >> 6) & 7, d = o & 63;
                const int bA = rA / NN, nA = rA - bA * NN;
                const int bB = rB / NN, nB = rB - bB * NN;
                const int bhA = bA * HH + h, bhB = bB * HH + h;
                const __half f0 = __float2half_rn(acc[mt][nt][0]);
                const __half f1 = __float2half_rn(acc[mt][nt][1]);
                const __half f2 = __float2half_rn(acc[mt][nt][2]);
                const __half f3 = __float2half_rn(acc[mt][nt][3]);
                if (part == 2) {
                    const size_t iA = ((size_t)bhA * DD + d) * NN + nA;
                    const size_t iB = ((size_t)bhB * DD + d) * NN + nB;
                    g_vtf[iA] = f0; g_vtf[iA + NN] = f1;
                    g_vtf[iB] = f2; g_vtf[iB + NN] = f3;
                } else {
                    __half* dst = (part == 0) ? g_qf : g_kf;
                    const size_t iA = ((size_t)bhA * NN + nA) * DD + d;
                    const size_t iB = ((size_t)bhB * NN + nB) * DD + d;
                    *(uint32_t*)&dst[iA] = pack2h(f0, f1);
                    *(uint32_t*)&dst[iB] = pack2h(f2, f3);
                }
            } else {
                const float b0 = bias[o], b1 = bias[o + 1];
                *(float2*)&out[(size_t)rA * CC + o] =
                    make_float2(acc[mt][nt][0] + b0, acc[mt][nt][1] + b1);
                *(float2*)&out[(size_t)rB * CC + o] =
                    make_float2(acc[mt][nt][2] + b0, acc[mt][nt][3] + b1);
            }
        }
    }
}

// ---------------------------------------------------------------------------
// Flash attention, single-pass fp16 MMA. CTA = 128 queries x one (b,h),
// 8 warps x 16q. 64-key tiles, 2-stage cp.async, exp2-domain softmax.
// ---------------------------------------------------------------------------
constexpr int FSTR = 72;
constexpr int F_TILE = 64 * FSTR;        // elems per array
constexpr int F_STAGE = 2 * F_TILE;      // K, V
constexpr int F_SMEM = 2 * F_STAGE * 2;  // bytes = 36864

__global__ __launch_bounds__(256, 2)
void flash_mma(const float* __restrict__ temp, const float* __restrict__ lw) {
    extern __shared__ __half hmem[];

    const int tid = threadIdx.x;
    const int lane = tid & 31, warp = tid >> 5;
    const int q0 = blockIdx.x * 128;
    const int bh = blockIdx.y;
    const int h = bh & 7, b = bh >> 3;

    const __half* Qg = g_qf + (size_t)bh * NN * DD;
    const __half* Kg = g_kf + (size_t)bh * NN * DD;
    const __half* Vg = g_vtf + (size_t)bh * NN * DD;  // [d][n]

    const float scale2 = __expf(temp[h]) * LOG2E;
    const float wb2 = lw[h] * (LOG2E / 4418.0f);

    // ---- Stage Q (128x64 fp16) through smem, extract fragments ----
    {
        __half* Qs = hmem;  // 128*FSTR elems = 18432 B, fits in stage region
#pragma unroll
        for (int it = 0; it < 4; it++) {
            const int c = tid + 256 * it;          // 1024 chunks
            const int row = c >> 3, col = c & 7;
            const size_t g = (size_t)(q0 + row) * DD + col * 8;
            cpa16(s2u(&Qs[row * FSTR + col * 8]), &Qg[g]);
        }
        CP_COMMIT();
        CP_WAIT0();
    }
    __syncthreads();

    uint32_t qf[4][4];
#pragma unroll
    for (int s = 0; s < 4; s++) {
        const int off = (warp * 16 + (lane & 15)) * FSTR + s * 16 + (lane >> 4) * 8;
        ldsm_x4(qf[s], s2u(&hmem[off]));
    }
    __syncthreads();

    auto load_kv = [&](int s, int k0) {
        __half* base = hmem + s * F_STAGE;
#pragma unroll
        for (int it = 0; it < 2; it++) {
            const int c = tid + 256 * it;          // 512 chunks
            const int row = c >> 3, col = c & 7;
            const size_t gk = (size_t)(k0 + row) * DD + col * 8;
            const size_t gv = (size_t)row * NN + k0 + col * 8;
            const int so = row * FSTR + col * 8;
            cpa16(s2u(base + so), &Kg[gk]);
            cpa16(s2u(base + F_TILE + so), &Vg[gv]);
        }
        CP_COMMIT();
    };

    float oacc[8][4];
#pragma unroll
    for (int u = 0; u < 8; u++)
#pragma unroll
        for (int r = 0; r < 4; r++) oacc[u][r] = 0.0f;
    float mA = -1e30f, mB = -1e30f, lA = 0.0f, lB = 0.0f;

    const int qA = q0 + warp * 16 + (lane >> 2), qB = qA + 8;
    const float4 qlocA = g_loc[qA], qlocB = g_loc[qB];
    const float byA = 2.0f * wb2 * qlocA.x, bxA = 2.0f * wb2 * qlocA.y;
    const float byB = 2.0f * wb2 * qlocB.x, bxB = 2.0f * wb2 * qlocB.y;

    constexpr int NKT = NN / 64;  // 36
    load_kv(0, 0);
    for (int kt = 0; kt < NKT; kt++) {
        if (kt + 1 < NKT) { load_kv((kt + 1) & 1, (kt + 1) * 64); CP_WAIT1(); }
        else              { CP_WAIT0(); }
        __syncthreads();
        const __half* sK = hmem + (kt & 1) * F_STAGE;
        const __half* sV = sK + F_TILE;
        const int k0 = kt * 64;

        // S = Q @ K^T  (16 x 64 per warp)
        float sfr[8][4];
#pragma unroll
        for (int t = 0; t < 8; t++)
#pragma unroll
            for (int r = 0; r < 4; r++) sfr[t][r] = 0.0f;
#pragma unroll
        for (int t = 0; t < 8; t++) {
            const int base = (8 * t + (lane & 7)) * FSTR + (lane >> 3) * 8;
            uint32_t k0f[4], k1f[4];
            ldsm_x4(k0f, s2u(&sK[base]));
            ldsm_x4(k1f, s2u(&sK[base + 32]));
            mma16816h(sfr[t], qf[0], &k0f[0]);
            mma16816h(sfr[t], qf[1], &k0f[2]);
            mma16816h(sfr[t], qf[2], &k1f[0]);
            mma16816h(sfr[t], qf[3], &k1f[2]);
        }

        // scale + locality bias (LUT, log2 domain) + row max
        float tmA = -1e30f, tmB = -1e30f;
#pragma unroll
        for (int t = 0; t < 8; t++) {
#pragma unroll
            for (int j = 0; j < 2; j++) {
                const int k = k0 + 8 * t + 2 * (lane & 3) + j;
                const float4 kl4 = __ldg(&g_loc[k]);
                const float cA = fmaf(byA, kl4.x, fmaf(bxA, kl4.y, -wb2 * kl4.z));
                const float cB = fmaf(byB, kl4.x, fmaf(bxB, kl4.y, -wb2 * kl4.z));
                sfr[t][j]     = fmaf(sfr[t][j],     scale2, cA);
                sfr[t][2 + j] = fmaf(sfr[t][2 + j], scale2, cB);
                tmA = fmaxf(tmA, sfr[t][j]);
                tmB = fmaxf(tmB, sfr[t][2 + j]);
            }
        }
        tmA = fmaxf(tmA, __shfl_xor_sync(0xffffffffu, tmA, 1));
        tmA = fmaxf(tmA, __shfl_xor_sync(0xffffffffu, tmA, 2));
        tmB = fmaxf(tmB, __shfl_xor_sync(0xffffffffu, tmB, 1));
        tmB = fmaxf(tmB, __shfl_xor_sync(0xffffffffu, tmB, 2));
        const float mnA = fmaxf(mA, tmA), mnB = fmaxf(mB, tmB);
        const float facA = exp2f(mA - mnA), facB = exp2f(mB - mnB);
        mA = mnA; mB = mnB;

        // exp2 + pack P fragments (A-frag layout, fp16) in registers
        uint32_t pf[4][4];
        float rsA = 0.0f, rsB = 0.0f;
#pragma unroll
        for (int s = 0; s < 4; s++) {
            const float p0 = exp2f(sfr[2 * s][0] - mnA);
            const float p1 = exp2f(sfr[2 * s][1] - mnA);
            const float p2 = exp2f(sfr[2 * s][2] - mnB);
            const float p3 = exp2f(sfr[2 * s][3] - mnB);
            const float r0 = exp2f(sfr[2 * s + 1][0] - mnA);
            const float r1 = exp2f(sfr[2 * s + 1][1] - mnA);
            const float r2 = exp2f(sfr[2 * s + 1][2] - mnB);
            const float r3 = exp2f(sfr[2 * s + 1][3] - mnB);
            rsA += p0 + p1 + r0 + r1;
            rsB += p2 + p3 + r2 + r3;
            pf[s][0] = pack2h(__float2half_rn(p0), __float2half_rn(p1));
            pf[s][1] = pack2h(__float2half_rn(p2), __float2half_rn(p3));
            pf[s][2] = pack2h(__float2half_rn(r0), __float2half_rn(r1));
            pf[s][3] = pack2h(__float2half_rn(r2), __float2half_rn(r3));
        }
        rsA += __shfl_xor_sync(0xffffffffu, rsA, 1);
        rsA += __shfl_xor_sync(0xffffffffu, rsA, 2);
        rsB += __shfl_xor_sync(0xffffffffu, rsB, 1);
        rsB += __shfl_xor_sync(0xffffffffu, rsB, 2);
        lA = lA * facA + rsA;
        lB = lB * facB + rsB;
#pragma unroll
        for (int u = 0; u < 8; u++) {
            oacc[u][0] *= facA; oacc[u][1] *= facA;
            oacc[u][2] *= facB; oacc[u][3] *= facB;
        }

        // O += P @ V
#pragma unroll
        for (int u = 0; u < 8; u++) {
            const int base = (8 * u + (lane & 7)) * FSTR + (lane >> 3) * 8;
            uint32_t v0f[4], v1f[4];
            ldsm_x4(v0f, s2u(&sV[base]));
            ldsm_x4(v1f, s2u(&sV[base + 32]));
            mma16816h(oacc[u], pf[0], &v0f[0]);
            mma16816h(oacc[u], pf[1], &v0f[2]);
            mma16816h(oacc[u], pf[2], &v1f[0]);
            mma16816h(oacc[u], pf[3], &v1f[2]);
        }
        __syncthreads();
    }

    // epilogue: normalize, split, write att bf16 hi/lo [b][n][C]
    const float invA = 1.0f / lA, invB = 1.0f / lB;
    const size_t baseA = ((size_t)(b * NN + qA)) * CC + h * DD;
    const size_t baseB = ((size_t)(b * NN + qB)) * CC + h * DD;
#pragma unroll
    for (int u = 0; u < 8; u++) {
        const int c = 8 * u + 2 * (lane & 3);
        __nv_bfloat16 h0, l0, h1, l1;
        split2(oacc[u][0] * invA, h0, l0); split2(oacc[u][1] * invA, h1, l1);
        *(uint32_t*)&g_ath[baseA + c] = pack2(h0, h1);
        *(uint32_t*)&g_atl[baseA + c] = pack2(l0, l1);
        split2(oacc[u][2] * invB, h0, l0); split2(oacc[u][3] * invB, h1, l1);
        *(uint32_t*)&g_ath[baseB + c] = pack2(h0, h1);
        *(uint32_t*)&g_atl[baseB + c] = pack2(l0, l1);
    }
}

// ---------------------------------------------------------------------------
extern "C" void kernel_launch(void* const* d_in, const int* in_sizes, int n_in,
                              void* d_out, int out_size) {
    const float* x      = (const float*)d_in[0];
    const float* qkv_w  = (const float*)d_in[1];
    const float* proj_w = (const float*)d_in[2];
    const float* proj_b = (const float*)d_in[3];
    const float* temp   = (const float*)d_in[4];
    const float* lw     = (const float*)d_in[5];
    float* out = (float*)d_out;

    cudaFuncSetAttribute(mma_gemm<0>, cudaFuncAttributeMaxDynamicSharedMemorySize, G_SMEM);
    cudaFuncSetAttribute(mma_gemm<1>, cudaFuncAttributeMaxDynamicSharedMemorySize, G_SMEM);
    cudaFuncSetAttribute(flash_mma,   cudaFuncAttributeMaxDynamicSharedMemorySize, F_SMEM);

    const int prep_blocks = (int)((SX + SQW + SPW) / 4 / 256);
    prep_split<<<prep_blocks, 256>>>(x, qkv_w, proj_w);

    mma_gemm<0><<<dim3(M_TOT / 128, 1536 / 128), 256, G_SMEM>>>(nullptr, nullptr);

    flash_mma<<<dim3(NN / 128, BB * HH), 256, F_SMEM>>>(temp, lw);

    mma_gemm<1><<<dim3(M_TOT / 128, CC / 128), 256, G_SMEM>>>(proj_b, out);
}

// round 8
// speedup vs baseline: 2.0677x; 1.3349x over previous
#include <cuda_runtime.h>
#include <cuda_bf16.h>
#include <cuda_fp16.h>
#include <stdint.h>

// LocalitySelfAttention: B=8, N=2304 (48x48), C=512, H=8, D=64.
// All-fp16 tensor pipeline (fp32 accumulate): error ~2e-4 << 1e-3 threshold.
// cp.async 2-stage pipelines, ldmatrix frags, register-resident P.

constexpr int BB = 8;
constexpr int NN = 2304;
constexpr int CC = 512;
constexpr int HH = 8;
constexpr int DD = 64;
constexpr int GG = 48;
constexpr int M_TOT = BB * NN;          // 18432
constexpr size_t SX  = (size_t)M_TOT * CC;   // 9437184 (= BB*HH*NN*DD)
constexpr size_t SQW = (size_t)1536 * 512;
constexpr size_t SPW = (size_t)512 * 512;
constexpr float LOG2E = 1.4426950408889634f;

__device__ __half g_xf[SX];          // x fp16
__device__ __half g_wqf[SQW];        // Wqkv fp16
__device__ __half g_wpf[SPW];        // Wproj fp16
__device__ __half g_qf[SX];          // [bh][n][d]
__device__ __half g_kf[SX];          // [bh][n][d]
__device__ __half g_vtf[SX];         // [bh][d][n] (transposed)
__device__ __half g_atf[SX];         // [b][n][C]
__device__ float4 g_loc[NN];         // (ky, kx, ky^2+kx^2, 0)

__device__ __forceinline__ uint32_t pack2h(__half a, __half b) {
    __half2 t; t.x = a; t.y = b;
    return *reinterpret_cast<uint32_t*>(&t);
}
__device__ __forceinline__ void mma16816h(float* c, const uint32_t* a, const uint32_t* b) {
    asm volatile(
        "mma.sync.aligned.m16n8k16.row.col.f32.f16.f16.f32 "
        "{%0,%1,%2,%3}, {%4,%5,%6,%7}, {%8,%9}, {%0,%1,%2,%3};"
        : "+f"(c[0]), "+f"(c[1]), "+f"(c[2]), "+f"(c[3])
        : "r"(a[0]), "r"(a[1]), "r"(a[2]), "r"(a[3]), "r"(b[0]), "r"(b[1]));
}
__device__ __forceinline__ void ldsm_x4(uint32_t* r, uint32_t addr) {
    asm volatile("ldmatrix.sync.aligned.m8n8.x4.shared.b16 {%0,%1,%2,%3}, [%4];"
        : "=r"(r[0]), "=r"(r[1]), "=r"(r[2]), "=r"(r[3]) : "r"(addr));
}
__device__ __forceinline__ uint32_t s2u(const void* p) {
    return (uint32_t)__cvta_generic_to_shared(p);
}
__device__ __forceinline__ void cpa16(uint32_t s, const void* g) {
    asm volatile("cp.async.ca.shared.global [%0], [%1], 16;" :: "r"(s), "l"(g));
}
#define CP_COMMIT() asm volatile("cp.async.commit_group;")
#define CP_WAIT0()  asm volatile("cp.async.wait_group 0;")
#define CP_WAIT1()  asm volatile("cp.async.wait_group 1;")

// ---------------------------------------------------------------------------
// Prep: fp32 -> fp16 + locality LUT.
// ---------------------------------------------------------------------------
__global__ __launch_bounds__(256)
void prep_cvt(const float* __restrict__ x, const float* __restrict__ wq,
              const float* __restrict__ wp) {
    const size_t gid = (size_t)blockIdx.x * 256 + threadIdx.x;
    if (gid < NN) {
        const int y = (int)(gid / GG), xx = (int)(gid - (size_t)y * GG);
        const float fy = (float)y, fx = (float)xx;
        g_loc[gid] = make_float4(fy, fx, fy * fy + fx * fx, 0.0f);
    }
    const size_t i4 = gid * 4;
    const float* src; __half* dst; size_t off;
    if (i4 < SX)                  { src = x;  dst = g_xf;  off = i4; }
    else if (i4 < SX + SQW)       { src = wq; dst = g_wqf; off = i4 - SX; }
    else if (i4 < SX + SQW + SPW) { src = wp; dst = g_wpf; off = i4 - SX - SQW; }
    else return;
    const float4 v = *(const float4*)(src + off);
    *(uint32_t*)&dst[off]     = pack2h(__float2half_rn(v.x), __float2half_rn(v.y));
    *(uint32_t*)&dst[off + 2] = pack2h(__float2half_rn(v.z), __float2half_rn(v.w));
}

// ---------------------------------------------------------------------------
// GEMM fp16: block 128x128, k-chunk 32, 8 warps (2m x 4n), 2-stage pipe.
// MODE 0: x @ Wqkv^T -> q/k fp16 [bh][n][d], v fp16 transposed [bh][d][n].
// MODE 1: att @ Wproj^T + bias -> fp32 out.
// ---------------------------------------------------------------------------
constexpr int GSTR = 40;                // fp16 row stride (80 B)
constexpr int G_TILE = 128 * GSTR;
constexpr int G_STAGE = 2 * G_TILE;     // A, B
constexpr int G_SMEM = 2 * G_STAGE * 2; // bytes = 40960

template <int MODE>
__global__ __launch_bounds__(256, 2)
void mma_gemm(const float* __restrict__ bias, float* __restrict__ out) {
    extern __shared__ __half smem[];

    const __half* A = (MODE == 0) ? g_xf : g_atf;
    const __half* B = (MODE == 0) ? g_wqf : g_wpf;

    const int tid = threadIdx.x;
    const int lane = tid & 31, warp = tid >> 5;
    const int wm = warp >> 2, wn = warp & 3;
    const int bm = blockIdx.x * 128, bn = blockIdx.y * 128;

    auto load_stage = [&](int s, int k0) {
        __half* base = smem + s * G_STAGE;
#pragma unroll
        for (int it = 0; it < 2; it++) {
            const int c = tid + 256 * it;
            const int row = c >> 2, col = c & 3;   // col in 8-elem units
            const size_t ga = (size_t)(bm + row) * CC + k0 + col * 8;
            const size_t gb = (size_t)(bn + row) * CC + k0 + col * 8;
            const int so = row * GSTR + col * 8;
            cpa16(s2u(base + so), &A[ga]);
            cpa16(s2u(base + G_TILE + so), &B[gb]);
        }
        CP_COMMIT();
    };

    float acc[4][4][4];
#pragma unroll
    for (int i = 0; i < 4; i++)
#pragma unroll
        for (int j = 0; j < 4; j++)
#pragma unroll
            for (int r = 0; r < 4; r++) acc[i][j][r] = 0.0f;

    constexpr int NIT = CC / 32;
    load_stage(0, 0);
    for (int i = 0; i < NIT; i++) {
        if (i + 1 < NIT) { load_stage((i + 1) & 1, (i + 1) * 32); CP_WAIT1(); }
        else             { CP_WAIT0(); }
        __syncthreads();
        const __half* sA = smem + (i & 1) * G_STAGE;
        const __half* sB = sA + G_TILE;

        uint32_t bf[4][4];
#pragma unroll
        for (int nt = 0; nt < 4; nt++) {
            const int boff = (wn * 32 + nt * 8 + (lane & 7)) * GSTR + (lane >> 3) * 8;
            ldsm_x4(bf[nt], s2u(&sB[boff]));
        }
#pragma unroll
        for (int mt = 0; mt < 4; mt++) {
            uint32_t af[2][4];
#pragma unroll
            for (int s = 0; s < 2; s++) {
                const int aoff = (wm * 64 + mt * 16 + (lane & 15)) * GSTR + s * 16 + (lane >> 4) * 8;
                ldsm_x4(af[s], s2u(&sA[aoff]));
            }
#pragma unroll
            for (int s = 0; s < 2; s++)
#pragma unroll
                for (int nt = 0; nt < 4; nt++)
                    mma16816h(acc[mt][nt], af[s], &bf[nt][2 * s]);
        }
        __syncthreads();
    }

#pragma unroll
    for (int mt = 0; mt < 4; mt++) {
#pragma unroll
        for (int nt = 0; nt < 4; nt++) {
            const int rA = bm + wm * 64 + mt * 16 + (lane >> 2);
            const int rB = rA + 8;
            const int o = bn + wn * 32 + nt * 8 + 2 * (lane & 3);
            if (MODE == 0) {
                const int part = o >> 9, h = (o >> 6) & 7, d = o & 63;
                const int bA = rA / NN, nA = rA - bA * NN;
                const int bB = rB / NN, nB = rB - bB * NN;
                const int bhA = bA * HH + h, bhB = bB * HH + h;
                const __half f0 = __float2half_rn(acc[mt][nt][0]);
                const __half f1 = __float2half_rn(acc[mt][nt][1]);
                const __half f2 = __float2half_rn(acc[mt][nt][2]);
                const __half f3 = __float2half_rn(acc[mt][nt][3]);
                if (part == 2) {
                    const size_t iA = ((size_t)bhA * DD + d) * NN + nA;
                    const size_t iB = ((size_t)bhB * DD + d) * NN + nB;
                    g_vtf[iA] = f0; g_vtf[iA + NN] = f1;
                    g_vtf[iB] = f2; g_vtf[iB + NN] = f3;
                } else {
                    __half* dst = (part == 0) ? g_qf : g_kf;
                    const size_t iA = ((size_t)bhA * NN + nA) * DD + d;
                    const size_t iB = ((size_t)bhB * NN + nB) * DD + d;
                    *(uint32_t*)&dst[iA] = pack2h(f0, f1);
                    *(uint32_t*)&dst[iB] = pack2h(f2, f3);
                }
            } else {
                const float b0 = bias[o], b1 = bias[o + 1];
                *(float2*)&out[(size_t)rA * CC + o] =
                    make_float2(acc[mt][nt][0] + b0, acc[mt][nt][1] + b1);
                *(float2*)&out[(size_t)rB * CC + o] =
                    make_float2(acc[mt][nt][2] + b0, acc[mt][nt][3] + b1);
            }
        }
    }
}

// ---------------------------------------------------------------------------
// Flash attention, fp16 MMA. CTA = 128 queries x one (b,h), 8 warps x 16q.
// 64-key tiles, 2-stage cp.async, exp2-domain softmax, register P.
// ---------------------------------------------------------------------------
constexpr int FSTR = 72;
constexpr int F_TILE = 64 * FSTR;
constexpr int F_STAGE = 2 * F_TILE;      // K, V
constexpr int F_SMEM = 2 * F_STAGE * 2;  // 36864 B

__global__ __launch_bounds__(256, 2)
void flash_mma(const float* __restrict__ temp, const float* __restrict__ lw) {
    extern __shared__ __half hmem[];

    const int tid = threadIdx.x;
    const int lane = tid & 31, warp = tid >> 5;
    const int q0 = blockIdx.x * 128;
    const int bh = blockIdx.y;
    const int h = bh & 7, b = bh >> 3;

    const __half* Qg = g_qf + (size_t)bh * NN * DD;
    const __half* Kg = g_kf + (size_t)bh * NN * DD;
    const __half* Vg = g_vtf + (size_t)bh * NN * DD;  // [d][n]

    const float scale2 = __expf(temp[h]) * LOG2E;
    const float wb2 = lw[h] * (LOG2E / 4418.0f);

    // ---- Stage Q (128x64) through smem, extract fragments ----
    {
        __half* Qs = hmem;
#pragma unroll
        for (int it = 0; it < 4; it++) {
            const int c = tid + 256 * it;
            const int row = c >> 3, col = c & 7;
            const size_t g = (size_t)(q0 + row) * DD + col * 8;
            cpa16(s2u(&Qs[row * FSTR + col * 8]), &Qg[g]);
        }
        CP_COMMIT();
        CP_WAIT0();
    }
    __syncthreads();

    uint32_t qf[4][4];
#pragma unroll
    for (int s = 0; s < 4; s++) {
        const int off = (warp * 16 + (lane & 15)) * FSTR + s * 16 + (lane >> 4) * 8;
        ldsm_x4(qf[s], s2u(&hmem[off]));
    }
    __syncthreads();

    auto load_kv = [&](int s, int k0) {
        __half* base = hmem + s * F_STAGE;
#pragma unroll
        for (int it = 0; it < 2; it++) {
            const int c = tid + 256 * it;
            const int row = c >> 3, col = c & 7;
            const size_t gk = (size_t)(k0 + row) * DD + col * 8;
            const size_t gv = (size_t)row * NN + k0 + col * 8;
            const int so = row * FSTR + col * 8;
            cpa16(s2u(base + so), &Kg[gk]);
            cpa16(s2u(base + F_TILE + so), &Vg[gv]);
        }
        CP_COMMIT();
    };

    float oacc[8][4];
#pragma unroll
    for (int u = 0; u < 8; u++)
#pragma unroll
        for (int r = 0; r < 4; r++) oacc[u][r] = 0.0f;
    float mA = -1e30f, mB = -1e30f, lA = 0.0f, lB = 0.0f;

    const int qA = q0 + warp * 16 + (lane >> 2), qB = qA + 8;
    const float4 qlocA = g_loc[qA], qlocB = g_loc[qB];
    const float byA = 2.0f * wb2 * qlocA.x, bxA = 2.0f * wb2 * qlocA.y;
    const float byB = 2.0f * wb2 * qlocB.x, bxB = 2.0f * wb2 * qlocB.y;

    constexpr int NKT = NN / 64;  // 36
    load_kv(0, 0);
    for (int kt = 0; kt < NKT; kt++) {
        if (kt + 1 < NKT) { load_kv((kt + 1) & 1, (kt + 1) * 64); CP_WAIT1(); }
        else              { CP_WAIT0(); }
        __syncthreads();
        const __half* sK = hmem + (kt & 1) * F_STAGE;
        const __half* sV = sK + F_TILE;
        const int k0 = kt * 64;

        // S = Q @ K^T
        float sfr[8][4];
#pragma unroll
        for (int t = 0; t < 8; t++)
#pragma unroll
            for (int r = 0; r < 4; r++) sfr[t][r] = 0.0f;
#pragma unroll
        for (int t = 0; t < 8; t++) {
            const int base = (8 * t + (lane & 7)) * FSTR + (lane >> 3) * 8;
            uint32_t k0f[4], k1f[4];
            ldsm_x4(k0f, s2u(&sK[base]));
            ldsm_x4(k1f, s2u(&sK[base + 32]));
            mma16816h(sfr[t], qf[0], &k0f[0]);
            mma16816h(sfr[t], qf[1], &k0f[2]);
            mma16816h(sfr[t], qf[2], &k1f[0]);
            mma16816h(sfr[t], qf[3], &k1f[2]);
        }

        // scale + locality bias + row max
        float tmA = -1e30f, tmB = -1e30f;
#pragma unroll
        for (int t = 0; t < 8; t++) {
#pragma unroll
            for (int j = 0; j < 2; j++) {
                const int k = k0 + 8 * t + 2 * (lane & 3) + j;
                const float4 kl4 = __ldg(&g_loc[k]);
                const float cA = fmaf(byA, kl4.x, fmaf(bxA, kl4.y, -wb2 * kl4.z));
                const float cB = fmaf(byB, kl4.x, fmaf(bxB, kl4.y, -wb2 * kl4.z));
                sfr[t][j]     = fmaf(sfr[t][j],     scale2, cA);
                sfr[t][2 + j] = fmaf(sfr[t][2 + j], scale2, cB);
                tmA = fmaxf(tmA, sfr[t][j]);
                tmB = fmaxf(tmB, sfr[t][2 + j]);
            }
        }
        tmA = fmaxf(tmA, __shfl_xor_sync(0xffffffffu, tmA, 1));
        tmA = fmaxf(tmA, __shfl_xor_sync(0xffffffffu, tmA, 2));
        tmB = fmaxf(tmB, __shfl_xor_sync(0xffffffffu, tmB, 1));
        tmB = fmaxf(tmB, __shfl_xor_sync(0xffffffffu, tmB, 2));
        const float mnA = fmaxf(mA, tmA), mnB = fmaxf(mB, tmB);
        const float facA = exp2f(mA - mnA), facB = exp2f(mB - mnB);
        mA = mnA; mB = mnB;

        // exp2 + pack P fragments (fp16)
        uint32_t pf[4][4];
        float rsA = 0.0f, rsB = 0.0f;
#pragma unroll
        for (int s = 0; s < 4; s++) {
            const float p0 = exp2f(sfr[2 * s][0] - mnA);
            const float p1 = exp2f(sfr[2 * s][1] - mnA);
            const float p2 = exp2f(sfr[2 * s][2] - mnB);
            const float p3 = exp2f(sfr[2 * s][3] - mnB);
            const float r0 = exp2f(sfr[2 * s + 1][0] - mnA);
            const float r1 = exp2f(sfr[2 * s + 1][1] - mnA);
            const float r2 = exp2f(sfr[2 * s + 1][2] - mnB);
            const float r3 = exp2f(sfr[2 * s + 1][3] - mnB);
            rsA += p0 + p1 + r0 + r1;
            rsB += p2 + p3 + r2 + r3;
            pf[s][0] = pack2h(__float2half_rn(p0), __float2half_rn(p1));
            pf[s][1] = pack2h(__float2half_rn(p2), __float2half_rn(p3));
            pf[s][2] = pack2h(__float2half_rn(r0), __float2half_rn(r1));
            pf[s][3] = pack2h(__float2half_rn(r2), __float2half_rn(r3));
        }
        rsA += __shfl_xor_sync(0xffffffffu, rsA, 1);
        rsA += __shfl_xor_sync(0xffffffffu, rsA, 2);
        rsB += __shfl_xor_sync(0xffffffffu, rsB, 1);
        rsB += __shfl_xor_sync(0xffffffffu, rsB, 2);
        lA = lA * facA + rsA;
        lB = lB * facB + rsB;
#pragma unroll
        for (int u = 0; u < 8; u++) {
            oacc[u][0] *= facA; oacc[u][1] *= facA;
            oacc[u][2] *= facB; oacc[u][3] *= facB;
        }

        // O += P @ V
#pragma unroll
        for (int u = 0; u < 8; u++) {
            const int base = (8 * u + (lane & 7)) * FSTR + (lane >> 3) * 8;
            uint32_t v0f[4], v1f[4];
            ldsm_x4(v0f, s2u(&sV[base]));
            ldsm_x4(v1f, s2u(&sV[base + 32]));
            mma16816h(oacc[u], pf[0], &v0f[0]);
            mma16816h(oacc[u], pf[1], &v0f[2]);
            mma16816h(oacc[u], pf[2], &v1f[0]);
            mma16816h(oacc[u], pf[3], &v1f[2]);
        }
        __syncthreads();
    }

    // epilogue: normalize, write att fp16 [b][n][C]
    const float invA = 1.0f / lA, invB = 1.0f / lB;
    const size_t baseA = ((size_t)(b * NN + qA)) * CC + h * DD;
    const size_t baseB = ((size_t)(b * NN + qB)) * CC + h * DD;
#pragma unroll
    for (int u = 0; u < 8; u++) {
        const int c = 8 * u + 2 * (lane & 3);
        *(uint32_t*)&g_atf[baseA + c] = pack2h(__float2half_rn(oacc[u][0] * invA),
                                               __float2half_rn(oacc[u][1] * invA));
        *(uint32_t*)&g_atf[baseB + c] = pack2h(__float2half_rn(oacc[u][2] * invB),
                                               __float2half_rn(oacc[u][3] * invB));
    }
}

// ---------------------------------------------------------------------------
extern "C" void kernel_launch(void* const* d_in, const int* in_sizes, int n_in,
                              void* d_out, int out_size) {
    const float* x      = (const float*)d_in[0];
    const float* qkv_w  = (const float*)d_in[1];
    const float* proj_w = (const float*)d_in[2];
    const float* proj_b = (const float*)d_in[3];
    const float* temp   = (const float*)d_in[4];
    const float* lw     = (const float*)d_in[5];
    float* out = (float*)d_out;

    cudaFuncSetAttribute(mma_gemm<0>, cudaFuncAttributeMaxDynamicSharedMemorySize, G_SMEM);
    cudaFuncSetAttribute(mma_gemm<1>, cudaFuncAttributeMaxDynamicSharedMemorySize, G_SMEM);
    cudaFuncSetAttribute(flash_mma,   cudaFuncAttributeMaxDynamicSharedMemorySize, F_SMEM);

    const int prep_blocks = (int)((SX + SQW + SPW) / 4 / 256);
    prep_cvt<<<prep_blocks, 256>>>(x, qkv_w, proj_w);

    mma_gemm<0><<<dim3(M_TOT / 128, 1536 / 128), 256, G_SMEM>>>(nullptr, nullptr);

    flash_mma<<<dim3(NN / 128, BB * HH), 256, F_SMEM>>>(temp, lw);

    mma_gemm<1><<<dim3(M_TOT / 128, CC / 128), 256, G_SMEM>>>(proj_b, out);
}

// round 9
// speedup vs baseline: 2.2165x; 1.0719x over previous
#include <cuda_runtime.h>
#include <cuda_bf16.h>
#include <cuda_fp16.h>
#include <stdint.h>

// LocalitySelfAttention: B=8, N=2304 (48x48), C=512, H=8, D=64.
// All-fp16 tensor pipeline (fp32 accumulate). 3-stage cp.async pipelines.
// Flash: 32 q-rows per warp (two 16-row sub-tiles share K/V fragments).

constexpr int BB = 8;
constexpr int NN = 2304;
constexpr int CC = 512;
constexpr int HH = 8;
constexpr int DD = 64;
constexpr int GG = 48;
constexpr int M_TOT = BB * NN;          // 18432
constexpr size_t SX  = (size_t)M_TOT * CC;
constexpr size_t SQW = (size_t)1536 * 512;
constexpr size_t SPW = (size_t)512 * 512;
constexpr float LOG2E = 1.4426950408889634f;

__device__ __half g_xf[SX];
__device__ __half g_wqf[SQW];
__device__ __half g_wpf[SPW];
__device__ __half g_qf[SX];          // [bh][n][d]
__device__ __half g_kf[SX];          // [bh][n][d]
__device__ __half g_vtf[SX];         // [bh][d][n]
__device__ __half g_atf[SX];         // [b][n][C]
__device__ float4 g_loc[NN];

__device__ __forceinline__ uint32_t pack2h(__half a, __half b) {
    __half2 t; t.x = a; t.y = b;
    return *reinterpret_cast<uint32_t*>(&t);
}
__device__ __forceinline__ void mma16816h(float* c, const uint32_t* a, const uint32_t* b) {
    asm volatile(
        "mma.sync.aligned.m16n8k16.row.col.f32.f16.f16.f32 "
        "{%0,%1,%2,%3}, {%4,%5,%6,%7}, {%8,%9}, {%0,%1,%2,%3};"
        : "+f"(c[0]), "+f"(c[1]), "+f"(c[2]), "+f"(c[3])
        : "r"(a[0]), "r"(a[1]), "r"(a[2]), "r"(a[3]), "r"(b[0]), "r"(b[1]));
}
__device__ __forceinline__ void ldsm_x4(uint32_t* r, uint32_t addr) {
    asm volatile("ldmatrix.sync.aligned.m8n8.x4.shared.b16 {%0,%1,%2,%3}, [%4];"
        : "=r"(r[0]), "=r"(r[1]), "=r"(r[2]), "=r"(r[3]) : "r"(addr));
}
__device__ __forceinline__ uint32_t s2u(const void* p) {
    return (uint32_t)__cvta_generic_to_shared(p);
}
__device__ __forceinline__ void cpa16(uint32_t s, const void* g) {
    asm volatile("cp.async.ca.shared.global [%0], [%1], 16;" :: "r"(s), "l"(g));
}
#define CP_COMMIT() asm volatile("cp.async.commit_group;")
#define CP_WAIT0()  asm volatile("cp.async.wait_group 0;")
#define CP_WAIT1()  asm volatile("cp.async.wait_group 1;")
#define CP_WAIT2()  asm volatile("cp.async.wait_group 2;")

// ---------------------------------------------------------------------------
// Prep: fp32 -> fp16 + locality LUT.
// ---------------------------------------------------------------------------
__global__ __launch_bounds__(256)
void prep_cvt(const float* __restrict__ x, const float* __restrict__ wq,
              const float* __restrict__ wp) {
    const size_t gid = (size_t)blockIdx.x * 256 + threadIdx.x;
    if (gid < NN) {
        const int y = (int)(gid / GG), xx = (int)(gid - (size_t)y * GG);
        const float fy = (float)y, fx = (float)xx;
        g_loc[gid] = make_float4(fy, fx, fy * fy + fx * fx, 0.0f);
    }
    const size_t i4 = gid * 4;
    const float* src; __half* dst; size_t off;
    if (i4 < SX)                  { src = x;  dst = g_xf;  off = i4; }
    else if (i4 < SX + SQW)       { src = wq; dst = g_wqf; off = i4 - SX; }
    else if (i4 < SX + SQW + SPW) { src = wp; dst = g_wpf; off = i4 - SX - SQW; }
    else return;
    const float4 v = *(const float4*)(src + off);
    *(uint32_t*)&dst[off]     = pack2h(__float2half_rn(v.x), __float2half_rn(v.y));
    *(uint32_t*)&dst[off + 2] = pack2h(__float2half_rn(v.z), __float2half_rn(v.w));
}

// ---------------------------------------------------------------------------
// GEMM fp16: block 128x128, k-chunk 32, 8 warps (2m x 4n), 3-stage pipe.
// ---------------------------------------------------------------------------
constexpr int GSTR = 40;
constexpr int G_TILE = 128 * GSTR;
constexpr int G_STAGE = 2 * G_TILE;     // A, B
constexpr int G_SMEM = 3 * G_STAGE * 2; // 61440 B

template <int MODE>
__global__ __launch_bounds__(256, 2)
void mma_gemm(const float* __restrict__ bias, float* __restrict__ out) {
    extern __shared__ __half smem[];

    const __half* A = (MODE == 0) ? g_xf : g_atf;
    const __half* B = (MODE == 0) ? g_wqf : g_wpf;

    const int tid = threadIdx.x;
    const int lane = tid & 31, warp = tid >> 5;
    const int wm = warp >> 2, wn = warp & 3;
    const int bm = blockIdx.x * 128, bn = blockIdx.y * 128;

    auto load_stage = [&](int s, int k0) {
        __half* base = smem + s * G_STAGE;
#pragma unroll
        for (int it = 0; it < 2; it++) {
            const int c = tid + 256 * it;
            const int row = c >> 2, col = c & 3;
            const size_t ga = (size_t)(bm + row) * CC + k0 + col * 8;
            const size_t gb = (size_t)(bn + row) * CC + k0 + col * 8;
            const int so = row * GSTR + col * 8;
            cpa16(s2u(base + so), &A[ga]);
            cpa16(s2u(base + G_TILE + so), &B[gb]);
        }
        CP_COMMIT();
    };

    float acc[4][4][4];
#pragma unroll
    for (int i = 0; i < 4; i++)
#pragma unroll
        for (int j = 0; j < 4; j++)
#pragma unroll
            for (int r = 0; r < 4; r++) acc[i][j][r] = 0.0f;

    constexpr int NIT = CC / 32;   // 16
    load_stage(0, 0);
    load_stage(1, 32);
    for (int i = 0; i < NIT; i++) {
        if (i + 2 < NIT)      { load_stage((i + 2) % 3, (i + 2) * 32); CP_WAIT2(); }
        else if (i + 1 < NIT) { CP_WAIT1(); }
        else                  { CP_WAIT0(); }
        __syncthreads();
        const __half* sA = smem + (i % 3) * G_STAGE;
        const __half* sB = sA + G_TILE;

        uint32_t bf[4][4];
#pragma unroll
        for (int nt = 0; nt < 4; nt++) {
            const int boff = (wn * 32 + nt * 8 + (lane & 7)) * GSTR + (lane >> 3) * 8;
            ldsm_x4(bf[nt], s2u(&sB[boff]));
        }
#pragma unroll
        for (int mt = 0; mt < 4; mt++) {
            uint32_t af[2][4];
#pragma unroll
            for (int s = 0; s < 2; s++) {
                const int aoff = (wm * 64 + mt * 16 + (lane & 15)) * GSTR + s * 16 + (lane >> 4) * 8;
                ldsm_x4(af[s], s2u(&sA[aoff]));
            }
#pragma unroll
            for (int s = 0; s < 2; s++)
#pragma unroll
                for (int nt = 0; nt < 4; nt++)
                    mma16816h(acc[mt][nt], af[s], &bf[nt][2 * s]);
        }
        __syncthreads();
    }

#pragma unroll
    for (int mt = 0; mt < 4; mt++) {
#pragma unroll
        for (int nt = 0; nt < 4; nt++) {
            const int rA = bm + wm * 64 + mt * 16 + (lane >> 2);
            const int rB = rA + 8;
            const int o = bn + wn * 32 + nt * 8 + 2 * (lane & 3);
            if (MODE == 0) {
                const int part = o >> 9, h = (o >> 6) & 7, d = o & 63;
                const int bA = rA / NN, nA = rA - bA * NN;
                const int bB = rB / NN, nB = rB - bB * NN;
                const int bhA = bA * HH + h, bhB = bB * HH + h;
                const __half f0 = __float2half_rn(acc[mt][nt][0]);
                const __half f1 = __float2half_rn(acc[mt][nt][1]);
                const __half f2 = __float2half_rn(acc[mt][nt][2]);
                const __half f3 = __float2half_rn(acc[mt][nt][3]);
                if (part == 2) {
                    const size_t iA = ((size_t)bhA * DD + d) * NN + nA;
                    const size_t iB = ((size_t)bhB * DD + d) * NN + nB;
                    g_vtf[iA] = f0; g_vtf[iA + NN] = f1;
                    g_vtf[iB] = f2; g_vtf[iB + NN] = f3;
                } else {
                    __half* dst = (part == 0) ? g_qf : g_kf;
                    const size_t iA = ((size_t)bhA * NN + nA) * DD + d;
                    const size_t iB = ((size_t)bhB * NN + nB) * DD + d;
                    *(uint32_t*)&dst[iA] = pack2h(f0, f1);
                    *(uint32_t*)&dst[iB] = pack2h(f2, f3);
                }
            } else {
                const float b0 = bias[o], b1 = bias[o + 1];
                *(float2*)&out[(size_t)rA * CC + o] =
                    make_float2(acc[mt][nt][0] + b0, acc[mt][nt][1] + b1);
                *(float2*)&out[(size_t)rB * CC + o] =
                    make_float2(acc[mt][nt][2] + b0, acc[mt][nt][3] + b1);
            }
        }
    }
}

// ---------------------------------------------------------------------------
// Flash attention, fp16. CTA = 256 q x one (b,h), 8 warps x 32q (two 16-row
// sub-tiles g=0,1 sharing K/V fragment loads). 64-key tiles, 3-stage pipe,
// exp2-domain softmax, register-resident P.
// ---------------------------------------------------------------------------
constexpr int FSTR = 72;
constexpr int FQ_ELE = 256 * FSTR;       // Q region (fp16 elems)
constexpr int F_TILE = 64 * FSTR;
constexpr int F_STAGE = 2 * F_TILE;      // K, V
constexpr int F_SMEM = (FQ_ELE + 3 * F_STAGE) * 2;  // 92160 B

__global__ __launch_bounds__(256, 1)
void flash_mma(const float* __restrict__ temp, const float* __restrict__ lw) {
    extern __shared__ __half hmem[];
    __half* Qs  = hmem;
    __half* kvs = hmem + FQ_ELE;

    const int tid = threadIdx.x;
    const int lane = tid & 31, warp = tid >> 5;
    const int q0 = blockIdx.x * 256;
    const int bh = blockIdx.y;
    const int h = bh & 7, b = bh >> 3;

    const __half* Qg = g_qf + (size_t)bh * NN * DD;
    const __half* Kg = g_kf + (size_t)bh * NN * DD;
    const __half* Vg = g_vtf + (size_t)bh * NN * DD;  // [d][n]

    const float scale2 = __expf(temp[h]) * LOG2E;
    const float wb2 = lw[h] * (LOG2E / 4418.0f);

    // ---- Stage Q (256x64) into smem ----
#pragma unroll
    for (int it = 0; it < 8; it++) {
        const int c = tid + 256 * it;          // 2048 chunks
        const int row = c >> 3, col = c & 7;
        const size_t g = (size_t)(q0 + row) * DD + col * 8;
        cpa16(s2u(&Qs[row * FSTR + col * 8]), &Qg[g]);
    }
    CP_COMMIT();
    CP_WAIT0();
    __syncthreads();

    uint32_t qf[2][4][4];
#pragma unroll
    for (int g = 0; g < 2; g++)
#pragma unroll
        for (int s = 0; s < 4; s++) {
            const int off = (warp * 32 + g * 16 + (lane & 15)) * FSTR + s * 16 + (lane >> 4) * 8;
            ldsm_x4(qf[g][s], s2u(&Qs[off]));
        }

    auto load_kv = [&](int s, int k0) {
        __half* base = kvs + s * F_STAGE;
#pragma unroll
        for (int it = 0; it < 2; it++) {
            const int c = tid + 256 * it;
            const int row = c >> 3, col = c & 7;
            const size_t gk = (size_t)(k0 + row) * DD + col * 8;
            const size_t gv = (size_t)row * NN + k0 + col * 8;
            const int so = row * FSTR + col * 8;
            cpa16(s2u(base + so), &Kg[gk]);
            cpa16(s2u(base + F_TILE + so), &Vg[gv]);
        }
        CP_COMMIT();
    };

    float oacc[2][8][4];
#pragma unroll
    for (int g = 0; g < 2; g++)
#pragma unroll
        for (int u = 0; u < 8; u++)
#pragma unroll
            for (int r = 0; r < 4; r++) oacc[g][u][r] = 0.0f;
    float mrow[2][2], lsum[2][2];
#pragma unroll
    for (int g = 0; g < 2; g++) {
        mrow[g][0] = mrow[g][1] = -1e30f;
        lsum[g][0] = lsum[g][1] = 0.0f;
    }

    float byc[2][2], bxc[2][2], wzc = -wb2;
#pragma unroll
    for (int g = 0; g < 2; g++)
#pragma unroll
        for (int hf = 0; hf < 2; hf++) {
            const int q = q0 + warp * 32 + g * 16 + (lane >> 2) + hf * 8;
            const float4 ql4 = g_loc[q];
            byc[g][hf] = 2.0f * wb2 * ql4.x;
            bxc[g][hf] = 2.0f * wb2 * ql4.y;
        }

    constexpr int NKT = NN / 64;  // 36
    load_kv(0, 0);
    load_kv(1, 64);
    for (int kt = 0; kt < NKT; kt++) {
        if (kt + 2 < NKT)      { load_kv((kt + 2) % 3, (kt + 2) * 64); CP_WAIT2(); }
        else if (kt + 1 < NKT) { CP_WAIT1(); }
        else                   { CP_WAIT0(); }
        __syncthreads();
        const __half* sK = kvs + (kt % 3) * F_STAGE;
        const __half* sV = sK + F_TILE;
        const int k0 = kt * 64;

        // S = Q @ K^T : 32 x 64 per warp, K frags shared by both sub-tiles
        float sfr[2][8][4];
#pragma unroll
        for (int g = 0; g < 2; g++)
#pragma unroll
            for (int t = 0; t < 8; t++)
#pragma unroll
                for (int r = 0; r < 4; r++) sfr[g][t][r] = 0.0f;
#pragma unroll
        for (int t = 0; t < 8; t++) {
            const int base = (8 * t + (lane & 7)) * FSTR + (lane >> 3) * 8;
            uint32_t k0f[4], k1f[4];
            ldsm_x4(k0f, s2u(&sK[base]));
            ldsm_x4(k1f, s2u(&sK[base + 32]));
#pragma unroll
            for (int g = 0; g < 2; g++) {
                mma16816h(sfr[g][t], qf[g][0], &k0f[0]);
                mma16816h(sfr[g][t], qf[g][1], &k0f[2]);
                mma16816h(sfr[g][t], qf[g][2], &k1f[0]);
                mma16816h(sfr[g][t], qf[g][3], &k1f[2]);
            }
        }

        // scale + locality bias; LUT load shared across sub-tiles
#pragma unroll
        for (int t = 0; t < 8; t++) {
#pragma unroll
            for (int j = 0; j < 2; j++) {
                const int k = k0 + 8 * t + 2 * (lane & 3) + j;
                const float4 kl4 = __ldg(&g_loc[k]);
                const float wz = wzc * kl4.z;
#pragma unroll
                for (int g = 0; g < 2; g++) {
                    const float cA = fmaf(byc[g][0], kl4.x, fmaf(bxc[g][0], kl4.y, wz));
                    const float cB = fmaf(byc[g][1], kl4.x, fmaf(bxc[g][1], kl4.y, wz));
                    sfr[g][t][j]     = fmaf(sfr[g][t][j],     scale2, cA);
                    sfr[g][t][2 + j] = fmaf(sfr[g][t][2 + j], scale2, cB);
                }
            }
        }

        // softmax per sub-tile; pack P frags in registers
        uint32_t pf[2][4][4];
#pragma unroll
        for (int g = 0; g < 2; g++) {
            float tmA = -1e30f, tmB = -1e30f;
#pragma unroll
            for (int t = 0; t < 8; t++) {
                tmA = fmaxf(tmA, fmaxf(sfr[g][t][0], sfr[g][t][1]));
                tmB = fmaxf(tmB, fmaxf(sfr[g][t][2], sfr[g][t][3]));
            }
            tmA = fmaxf(tmA, __shfl_xor_sync(0xffffffffu, tmA, 1));
            tmA = fmaxf(tmA, __shfl_xor_sync(0xffffffffu, tmA, 2));
            tmB = fmaxf(tmB, __shfl_xor_sync(0xffffffffu, tmB, 1));
            tmB = fmaxf(tmB, __shfl_xor_sync(0xffffffffu, tmB, 2));
            const float mnA = fmaxf(mrow[g][0], tmA), mnB = fmaxf(mrow[g][1], tmB);
            const float facA = exp2f(mrow[g][0] - mnA), facB = exp2f(mrow[g][1] - mnB);
            mrow[g][0] = mnA; mrow[g][1] = mnB;

            float rsA = 0.0f, rsB = 0.0f;
#pragma unroll
            for (int s = 0; s < 4; s++) {
                const float p0 = exp2f(sfr[g][2 * s][0] - mnA);
                const float p1 = exp2f(sfr[g][2 * s][1] - mnA);
                const float p2 = exp2f(sfr[g][2 * s][2] - mnB);
                const float p3 = exp2f(sfr[g][2 * s][3] - mnB);
                const float r0 = exp2f(sfr[g][2 * s + 1][0] - mnA);
                const float r1 = exp2f(sfr[g][2 * s + 1][1] - mnA);
                const float r2 = exp2f(sfr[g][2 * s + 1][2] - mnB);
                const float r3 = exp2f(sfr[g][2 * s + 1][3] - mnB);
                rsA += p0 + p1 + r0 + r1;
                rsB += p2 + p3 + r2 + r3;
                pf[g][s][0] = pack2h(__float2half_rn(p0), __float2half_rn(p1));
                pf[g][s][1] = pack2h(__float2half_rn(p2), __float2half_rn(p3));
                pf[g][s][2] = pack2h(__float2half_rn(r0), __float2half_rn(r1));
                pf[g][s][3] = pack2h(__float2half_rn(r2), __float2half_rn(r3));
            }
            rsA += __shfl_xor_sync(0xffffffffu, rsA, 1);
            rsA += __shfl_xor_sync(0xffffffffu, rsA, 2);
            rsB += __shfl_xor_sync(0xffffffffu, rsB, 1);
            rsB += __shfl_xor_sync(0xffffffffu, rsB, 2);
            lsum[g][0] = lsum[g][0] * facA + rsA;
            lsum[g][1] = lsum[g][1] * facB + rsB;
#pragma unroll
            for (int u = 0; u < 8; u++) {
                oacc[g][u][0] *= facA; oacc[g][u][1] *= facA;
                oacc[g][u][2] *= facB; oacc[g][u][3] *= facB;
            }
        }

        // O += P @ V : V frags shared by both sub-tiles
#pragma unroll
        for (int u = 0; u < 8; u++) {
            const int base = (8 * u + (lane & 7)) * FSTR + (lane >> 3) * 8;
            uint32_t v0f[4], v1f[4];
            ldsm_x4(v0f, s2u(&sV[base]));
            ldsm_x4(v1f, s2u(&sV[base + 32]));
#pragma unroll
            for (int g = 0; g < 2; g++) {
                mma16816h(oacc[g][u], pf[g][0], &v0f[0]);
                mma16816h(oacc[g][u], pf[g][1], &v0f[2]);
                mma16816h(oacc[g][u], pf[g][2], &v1f[0]);
                mma16816h(oacc[g][u], pf[g][3], &v1f[2]);
            }
        }
        __syncthreads();
    }

    // epilogue: normalize, write att fp16 [b][n][C]
#pragma unroll
    for (int g = 0; g < 2; g++) {
        const float invA = 1.0f / lsum[g][0], invB = 1.0f / lsum[g][1];
        const int qA = q0 + warp * 32 + g * 16 + (lane >> 2);
        const size_t baseA = ((size_t)(b * NN + qA)) * CC + h * DD;
        const size_t baseB = ((size_t)(b * NN + qA + 8)) * CC + h * DD;
#pragma unroll
        for (int u = 0; u < 8; u++) {
            const int c = 8 * u + 2 * (lane & 3);
            *(uint32_t*)&g_atf[baseA + c] =
                pack2h(__float2half_rn(oacc[g][u][0] * invA),
                       __float2half_rn(oacc[g][u][1] * invA));
            *(uint32_t*)&g_atf[baseB + c] =
                pack2h(__float2half_rn(oacc[g][u][2] * invB),
                       __float2half_rn(oacc[g][u][3] * invB));
        }
    }
}

// ---------------------------------------------------------------------------
extern "C" void kernel_launch(void* const* d_in, const int* in_sizes, int n_in,
                              void* d_out, int out_size) {
    const float* x      = (const float*)d_in[0];
    const float* qkv_w  = (const float*)d_in[1];
    const float* proj_w = (const float*)d_in[2];
    const float* proj_b = (const float*)d_in[3];
    const float* temp   = (const float*)d_in[4];
    const float* lw     = (const float*)d_in[5];
    float* out = (float*)d_out;

    cudaFuncSetAttribute(mma_gemm<0>, cudaFuncAttributeMaxDynamicSharedMemorySize, G_SMEM);
    cudaFuncSetAttribute(mma_gemm<1>, cudaFuncAttributeMaxDynamicSharedMemorySize, G_SMEM);
    cudaFuncSetAttribute(flash_mma,   cudaFuncAttributeMaxDynamicSharedMemorySize, F_SMEM);

    const int prep_blocks = (int)((SX + SQW + SPW) / 4 / 256);
    prep_cvt<<<prep_blocks, 256>>>(x, qkv_w, proj_w);

    mma_gemm<0><<<dim3(M_TOT / 128, 1536 / 128), 256, G_SMEM>>>(nullptr, nullptr);

    flash_mma<<<dim3(NN / 256, BB * HH), 256, F_SMEM>>>(temp, lw);

    mma_gemm<1><<<dim3(M_TOT / 128, CC / 128), 256, G_SMEM>>>(proj_b, out);
}

// round 10
// speedup vs baseline: 2.6868x; 1.2122x over previous
#include <cuda_runtime.h>
#include <cuda_bf16.h>
#include <cuda_fp16.h>
#include <stdint.h>

// LocalitySelfAttention: B=8, N=2304 (48x48), C=512, H=8, D=64.
// All-fp16 tensor pipeline (fp32 accumulate).
// Locality bias + temperature folded into augmented QK^T (D 64->80).
// Fixed-shift exp2 softmax (no online max). 3-stage cp.async pipelines.

constexpr int BB = 8;
constexpr int NN = 2304;
constexpr int CC = 512;
constexpr int HH = 8;
constexpr int DD = 64;
constexpr int DQ = 80;                   // augmented head dim
constexpr int GG = 48;
constexpr int M_TOT = BB * NN;           // 18432
constexpr size_t SX  = (size_t)M_TOT * CC;
constexpr size_t SQK = (size_t)BB * HH * NN * DQ;  // aug q/k
constexpr size_t SQW = (size_t)1536 * 512;
constexpr size_t SPW = (size_t)512 * 512;
constexpr float LOG2E = 1.4426950408889634f;
constexpr float M0 = 8.0f;               // fixed softmax shift (log2 domain)

__device__ __half g_xf[SX];
__device__ __half g_wqf[SQW];
__device__ __half g_wpf[SPW];
__device__ __half g_qf[SQK];         // [bh][n][80]: scale2*q | qy/8, qx/8, -1/8, 0..
__device__ __half g_kf[SQK];         // [bh][n][80]: k | 16w*ky, 16w*kx, 8w*kz, 0..
__device__ __half g_vtf[SX];         // [bh][d][n]
__device__ __half g_atf[SX];         // [b][n][C]

__device__ __forceinline__ uint32_t pack2h(__half a, __half b) {
    __half2 t; t.x = a; t.y = b;
    return *reinterpret_cast<uint32_t*>(&t);
}
__device__ __forceinline__ void mma16816h(float* c, const uint32_t* a, const uint32_t* b) {
    asm volatile(
        "mma.sync.aligned.m16n8k16.row.col.f32.f16.f16.f32 "
        "{%0,%1,%2,%3}, {%4,%5,%6,%7}, {%8,%9}, {%0,%1,%2,%3};"
        : "+f"(c[0]), "+f"(c[1]), "+f"(c[2]), "+f"(c[3])
        : "r"(a[0]), "r"(a[1]), "r"(a[2]), "r"(a[3]), "r"(b[0]), "r"(b[1]));
}
__device__ __forceinline__ void ldsm_x4(uint32_t* r, uint32_t addr) {
    asm volatile("ldmatrix.sync.aligned.m8n8.x4.shared.b16 {%0,%1,%2,%3}, [%4];"
        : "=r"(r[0]), "=r"(r[1]), "=r"(r[2]), "=r"(r[3]) : "r"(addr));
}
__device__ __forceinline__ void ldsm_x2(uint32_t* r, uint32_t addr) {
    asm volatile("ldmatrix.sync.aligned.m8n8.x2.shared.b16 {%0,%1}, [%2];"
        : "=r"(r[0]), "=r"(r[1]) : "r"(addr));
}
__device__ __forceinline__ uint32_t s2u(const void* p) {
    return (uint32_t)__cvta_generic_to_shared(p);
}
__device__ __forceinline__ void cpa16(uint32_t s, const void* g) {
    asm volatile("cp.async.ca.shared.global [%0], [%1], 16;" :: "r"(s), "l"(g));
}
#define CP_COMMIT() asm volatile("cp.async.commit_group;")
#define CP_WAIT0()  asm volatile("cp.async.wait_group 0;")
#define CP_WAIT1()  asm volatile("cp.async.wait_group 1;")
#define CP_WAIT2()  asm volatile("cp.async.wait_group 2;")

// ---------------------------------------------------------------------------
// Prep: fp32 -> fp16.
// ---------------------------------------------------------------------------
__global__ __launch_bounds__(256)
void prep_cvt(const float* __restrict__ x, const float* __restrict__ wq,
              const float* __restrict__ wp) {
    const size_t gid = (size_t)blockIdx.x * 256 + threadIdx.x;
    const size_t i4 = gid * 4;
    const float* src; __half* dst; size_t off;
    if (i4 < SX)                  { src = x;  dst = g_xf;  off = i4; }
    else if (i4 < SX + SQW)       { src = wq; dst = g_wqf; off = i4 - SX; }
    else if (i4 < SX + SQW + SPW) { src = wp; dst = g_wpf; off = i4 - SX - SQW; }
    else return;
    const float4 v = *(const float4*)(src + off);
    *(uint32_t*)&dst[off]     = pack2h(__float2half_rn(v.x), __float2half_rn(v.y));
    *(uint32_t*)&dst[off + 2] = pack2h(__float2half_rn(v.z), __float2half_rn(v.w));
}

// ---------------------------------------------------------------------------
// Aug fill: write the 16 augmentation columns of q and k per (bh, n).
// ---------------------------------------------------------------------------
__global__ __launch_bounds__(256)
void aug_fill(const float* __restrict__ lw) {
    const int idx = blockIdx.x * 256 + threadIdx.x;
    if (idx >= BB * HH * NN) return;
    const int bh = idx / NN, n = idx - bh * NN;
    const int h = bh & 7;
    const int y = n / GG, x = n - y * GG;
    const float wb2 = lw[h] * (LOG2E / 4418.0f);
    const float fy = (float)y, fx = (float)x;

    uint32_t qa[8], ka[8];
#pragma unroll
    for (int i = 0; i < 8; i++) { qa[i] = 0u; ka[i] = 0u; }
    qa[0] = pack2h(__float2half_rn(fy * 0.125f), __float2half_rn(fx * 0.125f));
    qa[1] = pack2h(__float2half_rn(-0.125f), __float2half_rn(0.0f));
    ka[0] = pack2h(__float2half_rn(16.0f * wb2 * fy), __float2half_rn(16.0f * wb2 * fx));
    ka[1] = pack2h(__float2half_rn(8.0f * wb2 * (fy * fy + fx * fx)), __float2half_rn(0.0f));

    uint32_t* qd = (uint32_t*)(g_qf + ((size_t)bh * NN + n) * DQ + 64);
    uint32_t* kd = (uint32_t*)(g_kf + ((size_t)bh * NN + n) * DQ + 64);
#pragma unroll
    for (int i = 0; i < 8; i++) { qd[i] = qa[i]; kd[i] = ka[i]; }
}

// ---------------------------------------------------------------------------
// GEMM fp16: block 128x128, k-chunk 32, 8 warps (2m x 4n), 3-stage pipe.
// MODE 0: x @ Wqkv^T -> q (scaled by exp(temp)*LOG2E) / k at stride 80,
//         v transposed [bh][d][n].
// MODE 1: att @ Wproj^T + bias -> fp32 out.
// ---------------------------------------------------------------------------
constexpr int GSTR = 40;
constexpr int G_TILE = 128 * GSTR;
constexpr int G_STAGE = 2 * G_TILE;
constexpr int G_SMEM = 3 * G_STAGE * 2;

template <int MODE>
__global__ __launch_bounds__(256, 2)
void mma_gemm(const float* __restrict__ bias, const float* __restrict__ temp,
              float* __restrict__ out) {
    extern __shared__ __half smem[];

    const __half* A = (MODE == 0) ? g_xf : g_atf;
    const __half* B = (MODE == 0) ? g_wqf : g_wpf;

    const int tid = threadIdx.x;
    const int lane = tid & 31, warp = tid >> 5;
    const int wm = warp >> 2, wn = warp & 3;
    const int bm = blockIdx.x * 128, bn = blockIdx.y * 128;

    auto load_stage = [&](int s, int k0) {
        __half* base = smem + s * G_STAGE;
#pragma unroll
        for (int it = 0; it < 2; it++) {
            const int c = tid + 256 * it;
            const int row = c >> 2, col = c & 3;
            const size_t ga = (size_t)(bm + row) * CC + k0 + col * 8;
            const size_t gb = (size_t)(bn + row) * CC + k0 + col * 8;
            const int so = row * GSTR + col * 8;
            cpa16(s2u(base + so), &A[ga]);
            cpa16(s2u(base + G_TILE + so), &B[gb]);
        }
        CP_COMMIT();
    };

    float acc[4][4][4];
#pragma unroll
    for (int i = 0; i < 4; i++)
#pragma unroll
        for (int j = 0; j < 4; j++)
#pragma unroll
            for (int r = 0; r < 4; r++) acc[i][j][r] = 0.0f;

    constexpr int NIT = CC / 32;
    load_stage(0, 0);
    load_stage(1, 32);
    for (int i = 0; i < NIT; i++) {
        if (i + 2 < NIT)      { load_stage((i + 2) % 3, (i + 2) * 32); CP_WAIT2(); }
        else if (i + 1 < NIT) { CP_WAIT1(); }
        else                  { CP_WAIT0(); }
        __syncthreads();
        const __half* sA = smem + (i % 3) * G_STAGE;
        const __half* sB = sA + G_TILE;

        uint32_t bf[4][4];
#pragma unroll
        for (int nt = 0; nt < 4; nt++) {
            const int boff = (wn * 32 + nt * 8 + (lane & 7)) * GSTR + (lane >> 3) * 8;
            ldsm_x4(bf[nt], s2u(&sB[boff]));
        }
#pragma unroll
        for (int mt = 0; mt < 4; mt++) {
            uint32_t af[2][4];
#pragma unroll
            for (int s = 0; s < 2; s++) {
                const int aoff = (wm * 64 + mt * 16 + (lane & 15)) * GSTR + s * 16 + (lane >> 4) * 8;
                ldsm_x4(af[s], s2u(&sA[aoff]));
            }
#pragma unroll
            for (int s = 0; s < 2; s++)
#pragma unroll
                for (int nt = 0; nt < 4; nt++)
                    mma16816h(acc[mt][nt], af[s], &bf[nt][2 * s]);
        }
        __syncthreads();
    }

#pragma unroll
    for (int mt = 0; mt < 4; mt++) {
#pragma unroll
        for (int nt = 0; nt < 4; nt++) {
            const int rA = bm + wm * 64 + mt * 16 + (lane >> 2);
            const int rB = rA + 8;
            const int o = bn + wn * 32 + nt * 8 + 2 * (lane & 3);
            if (MODE == 0) {
                const int part = o >> 9, h = (o >> 6) & 7, d = o & 63;
                const int bA = rA / NN, nA = rA - bA * NN;
                const int bB = rB / NN, nB = rB - bB * NN;
                const int bhA = bA * HH + h, bhB = bB * HH + h;
                float sc = 1.0f;
                if (part == 0) sc = __expf(temp[h]) * LOG2E;  // fold temp into q
                const __half f0 = __float2half_rn(acc[mt][nt][0] * sc);
                const __half f1 = __float2half_rn(acc[mt][nt][1] * sc);
                const __half f2 = __float2half_rn(acc[mt][nt][2] * sc);
                const __half f3 = __float2half_rn(acc[mt][nt][3] * sc);
                if (part == 2) {
                    const size_t iA = ((size_t)bhA * DD + d) * NN + nA;
                    const size_t iB = ((size_t)bhB * DD + d) * NN + nB;
                    g_vtf[iA] = f0; g_vtf[iA + NN] = f1;
                    g_vtf[iB] = f2; g_vtf[iB + NN] = f3;
                } else {
                    __half* dst = (part == 0) ? g_qf : g_kf;
                    const size_t iA = ((size_t)bhA * NN + nA) * DQ + d;
                    const size_t iB = ((size_t)bhB * NN + nB) * DQ + d;
                    *(uint32_t*)&dst[iA] = pack2h(f0, f1);
                    *(uint32_t*)&dst[iB] = pack2h(f2, f3);
                }
            } else {
                const float b0 = bias[o], b1 = bias[o + 1];
                *(float2*)&out[(size_t)rA * CC + o] =
                    make_float2(acc[mt][nt][0] + b0, acc[mt][nt][1] + b1);
                *(float2*)&out[(size_t)rB * CC + o] =
                    make_float2(acc[mt][nt][2] + b0, acc[mt][nt][3] + b1);
            }
        }
    }
}

// ---------------------------------------------------------------------------
// Flash attention, fp16, augmented D=80 QK^T (scale+bias inside MMA),
// fixed-shift exp2 softmax. CTA = 256 q x one (b,h), 8 warps x 32q
// (two 16-row sub-tiles share K/V fragments). 64-key tiles, 3-stage pipe.
// ---------------------------------------------------------------------------
constexpr int QSTR = 88;                 // Q/K smem stride (176 B, odd 16B mult)
constexpr int VSTR = 72;
constexpr int FQ_ELE = 256 * QSTR;       // 22528
constexpr int F_K_ELE = 64 * QSTR;       // 5632
constexpr int F_V_ELE = 64 * VSTR;       // 4608
constexpr int F_STAGE = F_K_ELE + F_V_ELE;
constexpr int F_SMEM = (FQ_ELE + 3 * F_STAGE) * 2;  // 106496 B

__global__ __launch_bounds__(256, 1)
void flash_mma() {
    extern __shared__ __half hmem[];
    __half* Qs  = hmem;
    __half* kvs = hmem + FQ_ELE;

    const int tid = threadIdx.x;
    const int lane = tid & 31, warp = tid >> 5;
    const int q0 = blockIdx.x * 256;
    const int bh = blockIdx.y;
    const int b = bh >> 3, h = bh & 7;

    const __half* Qg = g_qf + (size_t)bh * NN * DQ;
    const __half* Kg = g_kf + (size_t)bh * NN * DQ;
    const __half* Vg = g_vtf + (size_t)bh * NN * DD;  // [d][n]

    // ---- Stage Q (256 x 80) ----
#pragma unroll
    for (int it = 0; it < 8; it++) {       // cols 0..63
        const int c = tid + 256 * it;
        const int row = c >> 3, col = c & 7;
        cpa16(s2u(&Qs[row * QSTR + col * 8]), &Qg[(size_t)(q0 + row) * DQ + col * 8]);
    }
#pragma unroll
    for (int it = 0; it < 2; it++) {       // cols 64..79
        const int c = tid + 256 * it;
        const int row = c >> 1, col = 8 + (c & 1);
        cpa16(s2u(&Qs[row * QSTR + col * 8]), &Qg[(size_t)(q0 + row) * DQ + col * 8]);
    }
    CP_COMMIT();
    CP_WAIT0();
    __syncthreads();

    uint32_t qf[2][5][4];
#pragma unroll
    for (int g = 0; g < 2; g++)
#pragma unroll
        for (int s = 0; s < 5; s++) {
            const int off = (warp * 32 + g * 16 + (lane & 15)) * QSTR + s * 16 + (lane >> 4) * 8;
            ldsm_x4(qf[g][s], s2u(&Qs[off]));
        }

    auto load_kv = [&](int s, int k0) {
        __half* kb = kvs + s * F_STAGE;
        __half* vb = kb + F_K_ELE;
#pragma unroll
        for (int it = 0; it < 2; it++) {   // K cols 0..63 + V
            const int c = tid + 256 * it;
            const int row = c >> 3, col = c & 7;
            cpa16(s2u(&kb[row * QSTR + col * 8]), &Kg[(size_t)(k0 + row) * DQ + col * 8]);
            cpa16(s2u(&vb[row * VSTR + col * 8]), &Vg[(size_t)row * NN + k0 + col * 8]);
        }
        if (tid < 128) {                   // K cols 64..79
            const int row = tid >> 1, col = 8 + (tid & 1);
            cpa16(s2u(&kb[row * QSTR + col * 8]), &Kg[(size_t)(k0 + row) * DQ + col * 8]);
        }
        CP_COMMIT();
    };

    float oacc[2][8][4];
#pragma unroll
    for (int g = 0; g < 2; g++)
#pragma unroll
        for (int u = 0; u < 8; u++)
#pragma unroll
            for (int r = 0; r < 4; r++) oacc[g][u][r] = 0.0f;
    float lsum[2][2] = {{0.0f, 0.0f}, {0.0f, 0.0f}};

    constexpr int NKT = NN / 64;  // 36
    load_kv(0, 0);
    load_kv(1, 64);
    for (int kt = 0; kt < NKT; kt++) {
        if (kt + 2 < NKT)      { load_kv((kt + 2) % 3, (kt + 2) * 64); CP_WAIT2(); }
        else if (kt + 1 < NKT) { CP_WAIT1(); }
        else                   { CP_WAIT0(); }
        __syncthreads();
        const __half* sK = kvs + (kt % 3) * F_STAGE;
        const __half* sV = sK + F_K_ELE;

        // S' = Q' @ K'^T (scale + locality bias included), 32 x 64 per warp
        float sfr[2][8][4];
#pragma unroll
        for (int g = 0; g < 2; g++)
#pragma unroll
            for (int t = 0; t < 8; t++)
#pragma unroll
                for (int r = 0; r < 4; r++) sfr[g][t][r] = 0.0f;
#pragma unroll
        for (int t = 0; t < 8; t++) {
            const int base = (8 * t + (lane & 7)) * QSTR + (lane >> 3) * 8;
            const int base2 = (8 * t + (lane & 7)) * QSTR + 64 + ((lane >> 3) & 1) * 8;
            uint32_t k01[4], k23[4], k4[2];
            ldsm_x4(k01, s2u(&sK[base]));
            ldsm_x4(k23, s2u(&sK[base + 32]));
            ldsm_x2(k4,  s2u(&sK[base2]));
#pragma unroll
            for (int g = 0; g < 2; g++) {
                mma16816h(sfr[g][t], qf[g][0], &k01[0]);
                mma16816h(sfr[g][t], qf[g][1], &k01[2]);
                mma16816h(sfr[g][t], qf[g][2], &k23[0]);
                mma16816h(sfr[g][t], qf[g][3], &k23[2]);
                mma16816h(sfr[g][t], qf[g][4], k4);
            }
        }

        // fixed-shift exp2 softmax; pack P frags in registers
        uint32_t pf[2][4][4];
#pragma unroll
        for (int g = 0; g < 2; g++) {
#pragma unroll
            for (int s = 0; s < 4; s++) {
                const float p0 = exp2f(sfr[g][2 * s][0] - M0);
                const float p1 = exp2f(sfr[g][2 * s][1] - M0);
                const float p2 = exp2f(sfr[g][2 * s][2] - M0);
                const float p3 = exp2f(sfr[g][2 * s][3] - M0);
                const float r0 = exp2f(sfr[g][2 * s + 1][0] - M0);
                const float r1 = exp2f(sfr[g][2 * s + 1][1] - M0);
                const float r2 = exp2f(sfr[g][2 * s + 1][2] - M0);
                const float r3 = exp2f(sfr[g][2 * s + 1][3] - M0);
                lsum[g][0] += p0 + p1 + r0 + r1;
                lsum[g][1] += p2 + p3 + r2 + r3;
                pf[g][s][0] = pack2h(__float2half_rn(p0), __float2half_rn(p1));
                pf[g][s][1] = pack2h(__float2half_rn(p2), __float2half_rn(p3));
                pf[g][s][2] = pack2h(__float2half_rn(r0), __float2half_rn(r1));
                pf[g][s][3] = pack2h(__float2half_rn(r2), __float2half_rn(r3));
            }
        }

        // O += P @ V (V frags shared by both sub-tiles)
#pragma unroll
        for (int u = 0; u < 8; u++) {
            const int base = (8 * u + (lane & 7)) * VSTR + (lane >> 3) * 8;
            uint32_t v0f[4], v1f[4];
            ldsm_x4(v0f, s2u(&sV[base]));
            ldsm_x4(v1f, s2u(&sV[base + 32]));
#pragma unroll
            for (int g = 0; g < 2; g++) {
                mma16816h(oacc[g][u], pf[g][0], &v0f[0]);
                mma16816h(oacc[g][u], pf[g][1], &v0f[2]);
                mma16816h(oacc[g][u], pf[g][2], &v1f[0]);
                mma16816h(oacc[g][u], pf[g][3], &v1f[2]);
            }
        }
        __syncthreads();
    }

    // reduce lsum across the 4 lanes of each row group (once, at the end)
#pragma unroll
    for (int g = 0; g < 2; g++)
#pragma unroll
        for (int hf = 0; hf < 2; hf++) {
            lsum[g][hf] += __shfl_xor_sync(0xffffffffu, lsum[g][hf], 1);
            lsum[g][hf] += __shfl_xor_sync(0xffffffffu, lsum[g][hf], 2);
        }

    // epilogue: normalize, write att fp16 [b][n][C]
#pragma unroll
    for (int g = 0; g < 2; g++) {
        const float invA = 1.0f / lsum[g][0], invB = 1.0f / lsum[g][1];
        const int qA = q0 + warp * 32 + g * 16 + (lane >> 2);
        const size_t baseA = ((size_t)(b * NN + qA)) * CC + h * DD;
        const size_t baseB = ((size_t)(b * NN + qA + 8)) * CC + h * DD;
#pragma unroll
        for (int u = 0; u < 8; u++) {
            const int c = 8 * u + 2 * (lane & 3);
            *(uint32_t*)&g_atf[baseA + c] =
                pack2h(__float2half_rn(oacc[g][u][0] * invA),
                       __float2half_rn(oacc[g][u][1] * invA));
            *(uint32_t*)&g_atf[baseB + c] =
                pack2h(__float2half_rn(oacc[g][u][2] * invB),
                       __float2half_rn(oacc[g][u][3] * invB));
        }
    }
}

// ---------------------------------------------------------------------------
extern "C" void kernel_launch(void* const* d_in, const int* in_sizes, int n_in,
                              void* d_out, int out_size) {
    const float* x      = (const float*)d_in[0];
    const float* qkv_w  = (const float*)d_in[1];
    const float* proj_w = (const float*)d_in[2];
    const float* proj_b = (const float*)d_in[3];
    const float* temp   = (const float*)d_in[4];
    const float* lw     = (const float*)d_in[5];
    float* out = (float*)d_out;

    cudaFuncSetAttribute(mma_gemm<0>, cudaFuncAttributeMaxDynamicSharedMemorySize, G_SMEM);
    cudaFuncSetAttribute(mma_gemm<1>, cudaFuncAttributeMaxDynamicSharedMemorySize, G_SMEM);
    cudaFuncSetAttribute(flash_mma,   cudaFuncAttributeMaxDynamicSharedMemorySize, F_SMEM);

    const int prep_blocks = (int)((SX + SQW + SPW) / 4 / 256);
    prep_cvt<<<prep_blocks, 256>>>(x, qkv_w, proj_w);

    mma_gemm<0><<<dim3(M_TOT / 128, 1536 / 128), 256, G_SMEM>>>(nullptr, temp, nullptr);

    aug_fill<<<(BB * HH * NN + 255) / 256, 256>>>(lw);

    flash_mma<<<dim3(NN / 256, BB * HH), 256, F_SMEM>>>();

    mma_gemm<1><<<dim3(M_TOT / 128, CC / 128), 256, G_SMEM>>>(proj_b, nullptr, out);
}

// round 11
// speedup vs baseline: 2.7641x; 1.0287x over previous
#include <cuda_runtime.h>
#include <cuda_bf16.h>
#include <cuda_fp16.h>
#include <stdint.h>

// LocalitySelfAttention: B=8, N=2304 (48x48), C=512, H=8, D=64.
// All-fp16 tensor pipeline (fp32 accumulate).
// Locality bias + temperature + softmax shift folded into augmented QK^T (D 64->80).
// ex2.approx.f16x2 softmax; row-sums via ones-MMA on the tensor pipe.

constexpr int BB = 8;
constexpr int NN = 2304;
constexpr int CC = 512;
constexpr int HH = 8;
constexpr int DD = 64;
constexpr int DQ = 80;                   // augmented head dim
constexpr int GG = 48;
constexpr int M_TOT = BB * NN;           // 18432
constexpr size_t SX  = (size_t)M_TOT * CC;
constexpr size_t SQK = (size_t)BB * HH * NN * DQ;
constexpr size_t SQW = (size_t)1536 * 512;
constexpr size_t SPW = (size_t)512 * 512;
constexpr float LOG2E = 1.4426950408889634f;
constexpr float M0 = 8.0f;               // fixed softmax shift (folded into aug)

__device__ __half g_xf[SX];
__device__ __half g_wqf[SQW];
__device__ __half g_wpf[SPW];
__device__ __half g_qf[SQK];         // [bh][n][80]
__device__ __half g_kf[SQK];         // [bh][n][80]
__device__ __half g_vtf[SX];         // [bh][d][n]
__device__ __half g_atf[SX];         // [b][n][C]

__device__ __forceinline__ uint32_t pack2h(__half a, __half b) {
    __half2 t; t.x = a; t.y = b;
    return *reinterpret_cast<uint32_t*>(&t);
}
__device__ __forceinline__ void mma16816h(float* c, const uint32_t* a, const uint32_t* b) {
    asm volatile(
        "mma.sync.aligned.m16n8k16.row.col.f32.f16.f16.f32 "
        "{%0,%1,%2,%3}, {%4,%5,%6,%7}, {%8,%9}, {%0,%1,%2,%3};"
        : "+f"(c[0]), "+f"(c[1]), "+f"(c[2]), "+f"(c[3])
        : "r"(a[0]), "r"(a[1]), "r"(a[2]), "r"(a[3]), "r"(b[0]), "r"(b[1]));
}
__device__ __forceinline__ void ldsm_x4(uint32_t* r, uint32_t addr) {
    asm volatile("ldmatrix.sync.aligned.m8n8.x4.shared.b16 {%0,%1,%2,%3}, [%4];"
        : "=r"(r[0]), "=r"(r[1]), "=r"(r[2]), "=r"(r[3]) : "r"(addr));
}
__device__ __forceinline__ void ldsm_x2(uint32_t* r, uint32_t addr) {
    asm volatile("ldmatrix.sync.aligned.m8n8.x2.shared.b16 {%0,%1}, [%2];"
        : "=r"(r[0]), "=r"(r[1]) : "r"(addr));
}
__device__ __forceinline__ uint32_t s2u(const void* p) {
    return (uint32_t)__cvta_generic_to_shared(p);
}
__device__ __forceinline__ void cpa16(uint32_t s, const void* g) {
    asm volatile("cp.async.ca.shared.global [%0], [%1], 16;" :: "r"(s), "l"(g));
}
// pack (lo, hi) to f16x2 and exponentiate both halves in one MUFU op
__device__ __forceinline__ uint32_t exp2_f16x2(float lo, float hi) {
    uint32_t c, e;
    asm("cvt.rn.f16x2.f32 %0, %1, %2;" : "=r"(c) : "f"(hi), "f"(lo));
    asm("ex2.approx.f16x2 %0, %1;" : "=r"(e) : "r"(c));
    return e;
}
#define CP_COMMIT() asm volatile("cp.async.commit_group;")
#define CP_WAIT0()  asm volatile("cp.async.wait_group 0;")
#define CP_WAIT1()  asm volatile("cp.async.wait_group 1;")
#define CP_WAIT2()  asm volatile("cp.async.wait_group 2;")

// ---------------------------------------------------------------------------
// Prep: fp32 -> fp16.
// ---------------------------------------------------------------------------
__global__ __launch_bounds__(256)
void prep_cvt(const float* __restrict__ x, const float* __restrict__ wq,
              const float* __restrict__ wp) {
    const size_t gid = (size_t)blockIdx.x * 256 + threadIdx.x;
    const size_t i4 = gid * 4;
    const float* src; __half* dst; size_t off;
    if (i4 < SX)                  { src = x;  dst = g_xf;  off = i4; }
    else if (i4 < SX + SQW)       { src = wq; dst = g_wqf; off = i4 - SX; }
    else if (i4 < SX + SQW + SPW) { src = wp; dst = g_wpf; off = i4 - SX - SQW; }
    else return;
    const float4 v = *(const float4*)(src + off);
    *(uint32_t*)&dst[off]     = pack2h(__float2half_rn(v.x), __float2half_rn(v.y));
    *(uint32_t*)&dst[off + 2] = pack2h(__float2half_rn(v.z), __float2half_rn(v.w));
}

// ---------------------------------------------------------------------------
// Aug fill: 16 augmentation columns of q and k per (bh, n).
// q: [fy/8, fx/8, -1/8, -M0, 0...]   k: [16w*fy, 16w*fx, 8w*kz, 1, 0...]
// dot(aug_q, aug_k) = 2w*fy*ky + 2w*fx*kx - w*kz - M0  (log2-domain bias - shift)
// ---------------------------------------------------------------------------
__global__ __launch_bounds__(256)
void aug_fill(const float* __restrict__ lw) {
    const int idx = blockIdx.x * 256 + threadIdx.x;
    if (idx >= BB * HH * NN) return;
    const int bh = idx / NN, n = idx - bh * NN;
    const int h = bh & 7;
    const int y = n / GG, x = n - y * GG;
    const float wb2 = lw[h] * (LOG2E / 4418.0f);
    const float fy = (float)y, fx = (float)x;

    uint32_t qa[8], ka[8];
#pragma unroll
    for (int i = 0; i < 8; i++) { qa[i] = 0u; ka[i] = 0u; }
    qa[0] = pack2h(__float2half_rn(fy * 0.125f), __float2half_rn(fx * 0.125f));
    qa[1] = pack2h(__float2half_rn(-0.125f), __float2half_rn(-M0));
    ka[0] = pack2h(__float2half_rn(16.0f * wb2 * fy), __float2half_rn(16.0f * wb2 * fx));
    ka[1] = pack2h(__float2half_rn(8.0f * wb2 * (fy * fy + fx * fx)), __float2half_rn(1.0f));

    uint32_t* qd = (uint32_t*)(g_qf + ((size_t)bh * NN + n) * DQ + 64);
    uint32_t* kd = (uint32_t*)(g_kf + ((size_t)bh * NN + n) * DQ + 64);
#pragma unroll
    for (int i = 0; i < 8; i++) { qd[i] = qa[i]; kd[i] = ka[i]; }
}

// ---------------------------------------------------------------------------
// GEMM fp16: block 128x128, k-chunk 32, 8 warps (2m x 4n), 3-stage pipe.
// ---------------------------------------------------------------------------
constexpr int GSTR = 40;
constexpr int G_TILE = 128 * GSTR;
constexpr int G_STAGE = 2 * G_TILE;
constexpr int G_SMEM = 3 * G_STAGE * 2;

template <int MODE>
__global__ __launch_bounds__(256, 2)
void mma_gemm(const float* __restrict__ bias, const float* __restrict__ temp,
              float* __restrict__ out) {
    extern __shared__ __half smem[];

    const __half* A = (MODE == 0) ? g_xf : g_atf;
    const __half* B = (MODE == 0) ? g_wqf : g_wpf;

    const int tid = threadIdx.x;
    const int lane = tid & 31, warp = tid >> 5;
    const int wm = warp >> 2, wn = warp & 3;
    const int bm = blockIdx.x * 128, bn = blockIdx.y * 128;

    auto load_stage = [&](int s, int k0) {
        __half* base = smem + s * G_STAGE;
#pragma unroll
        for (int it = 0; it < 2; it++) {
            const int c = tid + 256 * it;
            const int row = c >> 2, col = c & 3;
            const size_t ga = (size_t)(bm + row) * CC + k0 + col * 8;
            const size_t gb = (size_t)(bn + row) * CC + k0 + col * 8;
            const int so = row * GSTR + col * 8;
            cpa16(s2u(base + so), &A[ga]);
            cpa16(s2u(base + G_TILE + so), &B[gb]);
        }
        CP_COMMIT();
    };

    float acc[4][4][4];
#pragma unroll
    for (int i = 0; i < 4; i++)
#pragma unroll
        for (int j = 0; j < 4; j++)
#pragma unroll
            for (int r = 0; r < 4; r++) acc[i][j][r] = 0.0f;

    constexpr int NIT = CC / 32;
    load_stage(0, 0);
    load_stage(1, 32);
    for (int i = 0; i < NIT; i++) {
        if (i + 2 < NIT)      { load_stage((i + 2) % 3, (i + 2) * 32); CP_WAIT2(); }
        else if (i + 1 < NIT) { CP_WAIT1(); }
        else                  { CP_WAIT0(); }
        __syncthreads();
        const __half* sA = smem + (i % 3) * G_STAGE;
        const __half* sB = sA + G_TILE;

        uint32_t bf[4][4];
#pragma unroll
        for (int nt = 0; nt < 4; nt++) {
            const int boff = (wn * 32 + nt * 8 + (lane & 7)) * GSTR + (lane >> 3) * 8;
            ldsm_x4(bf[nt], s2u(&sB[boff]));
        }
#pragma unroll
        for (int mt = 0; mt < 4; mt++) {
            uint32_t af[2][4];
#pragma unroll
            for (int s = 0; s < 2; s++) {
                const int aoff = (wm * 64 + mt * 16 + (lane & 15)) * GSTR + s * 16 + (lane >> 4) * 8;
                ldsm_x4(af[s], s2u(&sA[aoff]));
            }
#pragma unroll
            for (int s = 0; s < 2; s++)
#pragma unroll
                for (int nt = 0; nt < 4; nt++)
                    mma16816h(acc[mt][nt], af[s], &bf[nt][2 * s]);
        }
        __syncthreads();
    }

#pragma unroll
    for (int mt = 0; mt < 4; mt++) {
#pragma unroll
        for (int nt = 0; nt < 4; nt++) {
            const int rA = bm + wm * 64 + mt * 16 + (lane >> 2);
            const int rB = rA + 8;
            const int o = bn + wn * 32 + nt * 8 + 2 * (lane & 3);
            if (MODE == 0) {
                const int part = o >> 9, h = (o >> 6) & 7, d = o & 63;
                const int bA = rA / NN, nA = rA - bA * NN;
                const int bB = rB / NN, nB = rB - bB * NN;
                const int bhA = bA * HH + h, bhB = bB * HH + h;
                float sc = 1.0f;
                if (part == 0) sc = __expf(temp[h]) * LOG2E;  // fold temp into q
                const __half f0 = __float2half_rn(acc[mt][nt][0] * sc);
                const __half f1 = __float2half_rn(acc[mt][nt][1] * sc);
                const __half f2 = __float2half_rn(acc[mt][nt][2] * sc);
                const __half f3 = __float2half_rn(acc[mt][nt][3] * sc);
                if (part == 2) {
                    const size_t iA = ((size_t)bhA * DD + d) * NN + nA;
                    const size_t iB = ((size_t)bhB * DD + d) * NN + nB;
                    g_vtf[iA] = f0; g_vtf[iA + NN] = f1;
                    g_vtf[iB] = f2; g_vtf[iB + NN] = f3;
                } else {
                    __half* dst = (part == 0) ? g_qf : g_kf;
                    const size_t iA = ((size_t)bhA * NN + nA) * DQ + d;
                    const size_t iB = ((size_t)bhB * NN + nB) * DQ + d;
                    *(uint32_t*)&dst[iA] = pack2h(f0, f1);
                    *(uint32_t*)&dst[iB] = pack2h(f2, f3);
                }
            } else {
                const float b0 = bias[o], b1 = bias[o + 1];
                *(float2*)&out[(size_t)rA * CC + o] =
                    make_float2(acc[mt][nt][0] + b0, acc[mt][nt][1] + b1);
                *(float2*)&out[(size_t)rB * CC + o] =
                    make_float2(acc[mt][nt][2] + b0, acc[mt][nt][3] + b1);
            }
        }
    }
}

// ---------------------------------------------------------------------------
// Flash attention, fp16, augmented D=80 QK^T (scale+bias+shift in MMA),
// ex2.approx.f16x2 softmax, row sums via ones-MMA. CTA = 256 q x one (b,h),
// 8 warps x 32q (two 16-row sub-tiles share K/V frags). 3-stage pipe.
// ---------------------------------------------------------------------------
constexpr int QSTR = 88;
constexpr int VSTR = 72;
constexpr int FQ_ELE = 256 * QSTR;
constexpr int F_K_ELE = 64 * QSTR;
constexpr int F_V_ELE = 64 * VSTR;
constexpr int F_STAGE = F_K_ELE + F_V_ELE;
constexpr int F_SMEM = (FQ_ELE + 3 * F_STAGE) * 2;  // 106496 B

__global__ __launch_bounds__(256, 1)
void flash_mma() {
    extern __shared__ __half hmem[];
    __half* Qs  = hmem;
    __half* kvs = hmem + FQ_ELE;

    const int tid = threadIdx.x;
    const int lane = tid & 31, warp = tid >> 5;
    const int q0 = blockIdx.x * 256;
    const int bh = blockIdx.y;
    const int b = bh >> 3, h = bh & 7;

    const __half* Qg = g_qf + (size_t)bh * NN * DQ;
    const __half* Kg = g_kf + (size_t)bh * NN * DQ;
    const __half* Vg = g_vtf + (size_t)bh * NN * DD;  // [d][n]

    // ---- Stage Q (256 x 80) ----
#pragma unroll
    for (int it = 0; it < 8; it++) {
        const int c = tid + 256 * it;
        const int row = c >> 3, col = c & 7;
        cpa16(s2u(&Qs[row * QSTR + col * 8]), &Qg[(size_t)(q0 + row) * DQ + col * 8]);
    }
#pragma unroll
    for (int it = 0; it < 2; it++) {
        const int c = tid + 256 * it;
        const int row = c >> 1, col = 8 + (c & 1);
        cpa16(s2u(&Qs[row * QSTR + col * 8]), &Qg[(size_t)(q0 + row) * DQ + col * 8]);
    }
    CP_COMMIT();
    CP_WAIT0();
    __syncthreads();

    uint32_t qf[2][5][4];
#pragma unroll
    for (int g = 0; g < 2; g++)
#pragma unroll
        for (int s = 0; s < 5; s++) {
            const int off = (warp * 32 + g * 16 + (lane & 15)) * QSTR + s * 16 + (lane >> 4) * 8;
            ldsm_x4(qf[g][s], s2u(&Qs[off]));
        }

    auto load_kv = [&](int s, int k0) {
        __half* kb = kvs + s * F_STAGE;
        __half* vb = kb + F_K_ELE;
#pragma unroll
        for (int it = 0; it < 2; it++) {
            const int c = tid + 256 * it;
            const int row = c >> 3, col = c & 7;
            cpa16(s2u(&kb[row * QSTR + col * 8]), &Kg[(size_t)(k0 + row) * DQ + col * 8]);
            cpa16(s2u(&vb[row * VSTR + col * 8]), &Vg[(size_t)row * NN + k0 + col * 8]);
        }
        if (tid < 128) {
            const int row = tid >> 1, col = 8 + (tid & 1);
            cpa16(s2u(&kb[row * QSTR + col * 8]), &Kg[(size_t)(k0 + row) * DQ + col * 8]);
        }
        CP_COMMIT();
    };

    float oacc[2][8][4];
#pragma unroll
    for (int g = 0; g < 2; g++)
#pragma unroll
        for (int u = 0; u < 8; u++)
#pragma unroll
            for (int r = 0; r < 4; r++) oacc[g][u][r] = 0.0f;
    float lacc[2][4];   // row sums via ones-MMA (cols identical per row)
#pragma unroll
    for (int g = 0; g < 2; g++)
#pragma unroll
        for (int r = 0; r < 4; r++) lacc[g][r] = 0.0f;

    const uint32_t ONES2 = 0x3C003C00u;  // (1.0h, 1.0h)
    uint32_t onesb[2] = {ONES2, ONES2};

    constexpr int NKT = NN / 64;  // 36
    load_kv(0, 0);
    load_kv(1, 64);
    for (int kt = 0; kt < NKT; kt++) {
        if (kt + 2 < NKT)      { load_kv((kt + 2) % 3, (kt + 2) * 64); CP_WAIT2(); }
        else if (kt + 1 < NKT) { CP_WAIT1(); }
        else                   { CP_WAIT0(); }
        __syncthreads();
        const __half* sK = kvs + (kt % 3) * F_STAGE;
        const __half* sV = sK + F_K_ELE;

        // S' - M0 = Q' @ K'^T (scale, bias, shift all inside the MMA)
        float sfr[2][8][4];
#pragma unroll
        for (int g = 0; g < 2; g++)
#pragma unroll
            for (int t = 0; t < 8; t++)
#pragma unroll
                for (int r = 0; r < 4; r++) sfr[g][t][r] = 0.0f;
#pragma unroll
        for (int t = 0; t < 8; t++) {
            const int base = (8 * t + (lane & 7)) * QSTR + (lane >> 3) * 8;
            const int base2 = (8 * t + (lane & 7)) * QSTR + 64 + ((lane >> 3) & 1) * 8;
            uint32_t k01[4], k23[4], k4[2];
            ldsm_x4(k01, s2u(&sK[base]));
            ldsm_x4(k23, s2u(&sK[base + 32]));
            ldsm_x2(k4,  s2u(&sK[base2]));
#pragma unroll
            for (int g = 0; g < 2; g++) {
                mma16816h(sfr[g][t], qf[g][0], &k01[0]);
                mma16816h(sfr[g][t], qf[g][1], &k01[2]);
                mma16816h(sfr[g][t], qf[g][2], &k23[0]);
                mma16816h(sfr[g][t], qf[g][3], &k23[2]);
                mma16816h(sfr[g][t], qf[g][4], k4);
            }
        }

        // softmax: one cvt + one ex2.approx.f16x2 per value pair; sums via MMA
        uint32_t pf[2][4][4];
#pragma unroll
        for (int g = 0; g < 2; g++) {
#pragma unroll
            for (int s = 0; s < 4; s++) {
                pf[g][s][0] = exp2_f16x2(sfr[g][2 * s][0],     sfr[g][2 * s][1]);
                pf[g][s][1] = exp2_f16x2(sfr[g][2 * s][2],     sfr[g][2 * s][3]);
                pf[g][s][2] = exp2_f16x2(sfr[g][2 * s + 1][0], sfr[g][2 * s + 1][1]);
                pf[g][s][3] = exp2_f16x2(sfr[g][2 * s + 1][2], sfr[g][2 * s + 1][3]);
                mma16816h(lacc[g], pf[g][s], onesb);  // row-sum accumulation
            }
        }

        // O += P @ V (V frags shared by both sub-tiles)
#pragma unroll
        for (int u = 0; u < 8; u++) {
            const int base = (8 * u + (lane & 7)) * VSTR + (lane >> 3) * 8;
            uint32_t v0f[4], v1f[4];
            ldsm_x4(v0f, s2u(&sV[base]));
            ldsm_x4(v1f, s2u(&sV[base + 32]));
#pragma unroll
            for (int g = 0; g < 2; g++) {
                mma16816h(oacc[g][u], pf[g][0], &v0f[0]);
                mma16816h(oacc[g][u], pf[g][1], &v0f[2]);
                mma16816h(oacc[g][u], pf[g][2], &v1f[0]);
                mma16816h(oacc[g][u], pf[g][3], &v1f[2]);
            }
        }
        __syncthreads();
    }

    // epilogue: normalize by MMA-computed row sums, write att fp16 [b][n][C]
#pragma unroll
    for (int g = 0; g < 2; g++) {
        const float invA = 1.0f / lacc[g][0], invB = 1.0f / lacc[g][2];
        const int qA = q0 + warp * 32 + g * 16 + (lane >> 2);
        const size_t baseA = ((size_t)(b * NN + qA)) * CC + h * DD;
        const size_t baseB = ((size_t)(b * NN + qA + 8)) * CC + h * DD;
#pragma unroll
        for (int u = 0; u < 8; u++) {
            const int c = 8 * u + 2 * (lane & 3);
            *(uint32_t*)&g_atf[baseA + c] =
                pack2h(__float2half_rn(oacc[g][u][0] * invA),
                       __float2half_rn(oacc[g][u][1] * invA));
            *(uint32_t*)&g_atf[baseB + c] =
                pack2h(__float2half_rn(oacc[g][u][2] * invB),
                       __float2half_rn(oacc[g][u][3] * invB));
        }
    }
}

// ---------------------------------------------------------------------------
extern "C" void kernel_launch(void* const* d_in, const int* in_sizes, int n_in,
                              void* d_out, int out_size) {
    const float* x      = (const float*)d_in[0];
    const float* qkv_w  = (const float*)d_in[1];
    const float* proj_w = (const float*)d_in[2];
    const float* proj_b = (const float*)d_in[3];
    const float* temp   = (const float*)d_in[4];
    const float* lw     = (const float*)d_in[5];
    float* out = (float*)d_out;

    cudaFuncSetAttribute(mma_gemm<0>, cudaFuncAttributeMaxDynamicSharedMemorySize, G_SMEM);
    cudaFuncSetAttribute(mma_gemm<1>, cudaFuncAttributeMaxDynamicSharedMemorySize, G_SMEM);
    cudaFuncSetAttribute(flash_mma,   cudaFuncAttributeMaxDynamicSharedMemorySize, F_SMEM);

    const int prep_blocks = (int)((SX + SQW + SPW) / 4 / 256);
    prep_cvt<<<prep_blocks, 256>>>(x, qkv_w, proj_w);

    mma_gemm<0><<<dim3(M_TOT / 128, 1536 / 128), 256, G_SMEM>>>(nullptr, temp, nullptr);

    aug_fill<<<(BB * HH * NN + 255) / 256, 256>>>(lw);

    flash_mma<<<dim3(NN / 256, BB * HH), 256, F_SMEM>>>();

    mma_gemm<1><<<dim3(M_TOT / 128, CC / 128), 256, G_SMEM>>>(proj_b, nullptr, out);
}

// round 12
// speedup vs baseline: 2.7808x; 1.0061x over previous
#include <cuda_runtime.h>
#include <cuda_bf16.h>
#include <cuda_fp16.h>
#include <stdint.h>

// LocalitySelfAttention: B=8, N=2304 (48x48), C=512, H=8, D=64.
// All-fp16 tensor pipeline (fp32 accumulate).
// Locality bias + temperature + softmax shift folded into augmented QK^T (D 64->80).
// ex2.approx.f16x2 softmax; row-sums via ones-MMA.
// Flash: 128-thread CTAs (4 warps x 32q) -> 2 CTAs/SM to hide sync/MUFU stalls.

constexpr int BB = 8;
constexpr int NN = 2304;
constexpr int CC = 512;
constexpr int HH = 8;
constexpr int DD = 64;
constexpr int DQ = 80;
constexpr int GG = 48;
constexpr int M_TOT = BB * NN;
constexpr size_t SX  = (size_t)M_TOT * CC;
constexpr size_t SQK = (size_t)BB * HH * NN * DQ;
constexpr size_t SQW = (size_t)1536 * 512;
constexpr size_t SPW = (size_t)512 * 512;
constexpr float LOG2E = 1.4426950408889634f;
constexpr float M0 = 8.0f;

__device__ __half g_xf[SX];
__device__ __half g_wqf[SQW];
__device__ __half g_wpf[SPW];
__device__ __half g_qf[SQK];         // [bh][n][80]
__device__ __half g_kf[SQK];         // [bh][n][80]
__device__ __half g_vtf[SX];         // [bh][d][n]
__device__ __half g_atf[SX];         // [b][n][C]

__device__ __forceinline__ uint32_t pack2h(__half a, __half b) {
    __half2 t; t.x = a; t.y = b;
    return *reinterpret_cast<uint32_t*>(&t);
}
__device__ __forceinline__ void mma16816h(float* c, const uint32_t* a, const uint32_t* b) {
    asm volatile(
        "mma.sync.aligned.m16n8k16.row.col.f32.f16.f16.f32 "
        "{%0,%1,%2,%3}, {%4,%5,%6,%7}, {%8,%9}, {%0,%1,%2,%3};"
        : "+f"(c[0]), "+f"(c[1]), "+f"(c[2]), "+f"(c[3])
        : "r"(a[0]), "r"(a[1]), "r"(a[2]), "r"(a[3]), "r"(b[0]), "r"(b[1]));
}
__device__ __forceinline__ void ldsm_x4(uint32_t* r, uint32_t addr) {
    asm volatile("ldmatrix.sync.aligned.m8n8.x4.shared.b16 {%0,%1,%2,%3}, [%4];"
        : "=r"(r[0]), "=r"(r[1]), "=r"(r[2]), "=r"(r[3]) : "r"(addr));
}
__device__ __forceinline__ void ldsm_x2(uint32_t* r, uint32_t addr) {
    asm volatile("ldmatrix.sync.aligned.m8n8.x2.shared.b16 {%0,%1}, [%2];"
        : "=r"(r[0]), "=r"(r[1]) : "r"(addr));
}
__device__ __forceinline__ uint32_t s2u(const void* p) {
    return (uint32_t)__cvta_generic_to_shared(p);
}
__device__ __forceinline__ void cpa16(uint32_t s, const void* g) {
    asm volatile("cp.async.ca.shared.global [%0], [%1], 16;" :: "r"(s), "l"(g));
}
__device__ __forceinline__ uint32_t exp2_f16x2(float lo, float hi) {
    uint32_t c, e;
    asm("cvt.rn.f16x2.f32 %0, %1, %2;" : "=r"(c) : "f"(hi), "f"(lo));
    asm("ex2.approx.f16x2 %0, %1;" : "=r"(e) : "r"(c));
    return e;
}
#define CP_COMMIT() asm volatile("cp.async.commit_group;")
#define CP_WAIT0()  asm volatile("cp.async.wait_group 0;")
#define CP_WAIT1()  asm volatile("cp.async.wait_group 1;")
#define CP_WAIT2()  asm volatile("cp.async.wait_group 2;")

// ---------------------------------------------------------------------------
// Prep: fp32 -> fp16.
// ---------------------------------------------------------------------------
__global__ __launch_bounds__(256)
void prep_cvt(const float* __restrict__ x, const float* __restrict__ wq,
              const float* __restrict__ wp) {
    const size_t gid = (size_t)blockIdx.x * 256 + threadIdx.x;
    const size_t i4 = gid * 4;
    const float* src; __half* dst; size_t off;
    if (i4 < SX)                  { src = x;  dst = g_xf;  off = i4; }
    else if (i4 < SX + SQW)       { src = wq; dst = g_wqf; off = i4 - SX; }
    else if (i4 < SX + SQW + SPW) { src = wp; dst = g_wpf; off = i4 - SX - SQW; }
    else return;
    const float4 v = *(const float4*)(src + off);
    *(uint32_t*)&dst[off]     = pack2h(__float2half_rn(v.x), __float2half_rn(v.y));
    *(uint32_t*)&dst[off + 2] = pack2h(__float2half_rn(v.z), __float2half_rn(v.w));
}

// ---------------------------------------------------------------------------
// Aug fill: q: [fy/8, fx/8, -1/8, -M0, 0...]  k: [16w*fy, 16w*fx, 8w*kz, 1, 0...]
// ---------------------------------------------------------------------------
__global__ __launch_bounds__(256)
void aug_fill(const float* __restrict__ lw) {
    const int idx = blockIdx.x * 256 + threadIdx.x;
    if (idx >= BB * HH * NN) return;
    const int bh = idx / NN, n = idx - bh * NN;
    const int h = bh & 7;
    const int y = n / GG, x = n - y * GG;
    const float wb2 = lw[h] * (LOG2E / 4418.0f);
    const float fy = (float)y, fx = (float)x;

    uint32_t qa[8], ka[8];
#pragma unroll
    for (int i = 0; i < 8; i++) { qa[i] = 0u; ka[i] = 0u; }
    qa[0] = pack2h(__float2half_rn(fy * 0.125f), __float2half_rn(fx * 0.125f));
    qa[1] = pack2h(__float2half_rn(-0.125f), __float2half_rn(-M0));
    ka[0] = pack2h(__float2half_rn(16.0f * wb2 * fy), __float2half_rn(16.0f * wb2 * fx));
    ka[1] = pack2h(__float2half_rn(8.0f * wb2 * (fy * fy + fx * fx)), __float2half_rn(1.0f));

    uint32_t* qd = (uint32_t*)(g_qf + ((size_t)bh * NN + n) * DQ + 64);
    uint32_t* kd = (uint32_t*)(g_kf + ((size_t)bh * NN + n) * DQ + 64);
#pragma unroll
    for (int i = 0; i < 8; i++) { qd[i] = qa[i]; kd[i] = ka[i]; }
}

// ---------------------------------------------------------------------------
// GEMM fp16: block 128x128, k-chunk 32, 8 warps (2m x 4n), 3-stage pipe.
// ---------------------------------------------------------------------------
constexpr int GSTR = 40;
constexpr int G_TILE = 128 * GSTR;
constexpr int G_STAGE = 2 * G_TILE;
constexpr int G_SMEM = 3 * G_STAGE * 2;

template <int MODE>
__global__ __launch_bounds__(256, 2)
void mma_gemm(const float* __restrict__ bias, const float* __restrict__ temp,
              float* __restrict__ out) {
    extern __shared__ __half smem[];

    const __half* A = (MODE == 0) ? g_xf : g_atf;
    const __half* B = (MODE == 0) ? g_wqf : g_wpf;

    const int tid = threadIdx.x;
    const int lane = tid & 31, warp = tid >> 5;
    const int wm = warp >> 2, wn = warp & 3;
    const int bm = blockIdx.x * 128, bn = blockIdx.y * 128;

    auto load_stage = [&](int s, int k0) {
        __half* base = smem + s * G_STAGE;
#pragma unroll
        for (int it = 0; it < 2; it++) {
            const int c = tid + 256 * it;
            const int row = c >> 2, col = c & 3;
            const size_t ga = (size_t)(bm + row) * CC + k0 + col * 8;
            const size_t gb = (size_t)(bn + row) * CC + k0 + col * 8;
            const int so = row * GSTR + col * 8;
            cpa16(s2u(base + so), &A[ga]);
            cpa16(s2u(base + G_TILE + so), &B[gb]);
        }
        CP_COMMIT();
    };

    float acc[4][4][4];
#pragma unroll
    for (int i = 0; i < 4; i++)
#pragma unroll
        for (int j = 0; j < 4; j++)
#pragma unroll
            for (int r = 0; r < 4; r++) acc[i][j][r] = 0.0f;

    constexpr int NIT = CC / 32;
    load_stage(0, 0);
    load_stage(1, 32);
    for (int i = 0; i < NIT; i++) {
        if (i + 2 < NIT)      { load_stage((i + 2) % 3, (i + 2) * 32); CP_WAIT2(); }
        else if (i + 1 < NIT) { CP_WAIT1(); }
        else                  { CP_WAIT0(); }
        __syncthreads();
        const __half* sA = smem + (i % 3) * G_STAGE;
        const __half* sB = sA + G_TILE;

        uint32_t bf[4][4];
#pragma unroll
        for (int nt = 0; nt < 4; nt++) {
            const int boff = (wn * 32 + nt * 8 + (lane & 7)) * GSTR + (lane >> 3) * 8;
            ldsm_x4(bf[nt], s2u(&sB[boff]));
        }
#pragma unroll
        for (int mt = 0; mt < 4; mt++) {
            uint32_t af[2][4];
#pragma unroll
            for (int s = 0; s < 2; s++) {
                const int aoff = (wm * 64 + mt * 16 + (lane & 15)) * GSTR + s * 16 + (lane >> 4) * 8;
                ldsm_x4(af[s], s2u(&sA[aoff]));
            }
#pragma unroll
            for (int s = 0; s < 2; s++)
#pragma unroll
                for (int nt = 0; nt < 4; nt++)
                    mma16816h(acc[mt][nt], af[s], &bf[nt][2 * s]);
        }
        __syncthreads();
    }

#pragma unroll
    for (int mt = 0; mt < 4; mt++) {
#pragma unroll
        for (int nt = 0; nt < 4; nt++) {
            const int rA = bm + wm * 64 + mt * 16 + (lane >> 2);
            const int rB = rA + 8;
            const int o = bn + wn * 32 + nt * 8 + 2 * (lane & 3);
            if (MODE == 0) {
                const int part = o >> 9, h = (o >> 6) & 7, d = o & 63;
                const int bA = rA / NN, nA = rA - bA * NN;
                const int bB = rB / NN, nB = rB - bB * NN;
                const int bhA = bA * HH + h, bhB = bB * HH + h;
                float sc = 1.0f;
                if (part == 0) sc = __expf(temp[h]) * LOG2E;
                const __half f0 = __float2half_rn(acc[mt][nt][0] * sc);
                const __half f1 = __float2half_rn(acc[mt][nt][1] * sc);
                const __half f2 = __float2half_rn(acc[mt][nt][2] * sc);
                const __half f3 = __float2half_rn(acc[mt][nt][3] * sc);
                if (part == 2) {
                    const size_t iA = ((size_t)bhA * DD + d) * NN + nA;
                    const size_t iB = ((size_t)bhB * DD + d) * NN + nB;
                    g_vtf[iA] = f0; g_vtf[iA + NN] = f1;
                    g_vtf[iB] = f2; g_vtf[iB + NN] = f3;
                } else {
                    __half* dst = (part == 0) ? g_qf : g_kf;
                    const size_t iA = ((size_t)bhA * NN + nA) * DQ + d;
                    const size_t iB = ((size_t)bhB * NN + nB) * DQ + d;
                    *(uint32_t*)&dst[iA] = pack2h(f0, f1);
                    *(uint32_t*)&dst[iB] = pack2h(f2, f3);
                }
            } else {
                const float b0 = bias[o], b1 = bias[o + 1];
                *(float2*)&out[(size_t)rA * CC + o] =
                    make_float2(acc[mt][nt][0] + b0, acc[mt][nt][1] + b1);
                *(float2*)&out[(size_t)rB * CC + o] =
                    make_float2(acc[mt][nt][2] + b0, acc[mt][nt][3] + b1);
            }
        }
    }
}

// ---------------------------------------------------------------------------
// Flash attention, fp16, augmented D=80 QK^T, ex2.approx.f16x2 softmax,
// row sums via ones-MMA. CTA = 128 q x one (b,h), 4 warps x 32q
// (two 16-row sub-tiles share K/V frags). 3-stage pipe. 2 CTAs/SM.
// ---------------------------------------------------------------------------
constexpr int QSTR = 88;
constexpr int VSTR = 72;
constexpr int FQ_ELE = 128 * QSTR;       // 11264
constexpr int F_K_ELE = 64 * QSTR;       // 5632
constexpr int F_V_ELE = 64 * VSTR;       // 4608
constexpr int F_STAGE = F_K_ELE + F_V_ELE;
constexpr int F_SMEM = (FQ_ELE + 3 * F_STAGE) * 2;  // 83968 B

__global__ __launch_bounds__(128, 2)
void flash_mma() {
    extern __shared__ __half hmem[];
    __half* Qs  = hmem;
    __half* kvs = hmem + FQ_ELE;

    const int tid = threadIdx.x;
    const int lane = tid & 31, warp = tid >> 5;   // warp 0..3
    const int q0 = blockIdx.x * 128;
    const int bh = blockIdx.y;
    const int b = bh >> 3, h = bh & 7;

    const __half* Qg = g_qf + (size_t)bh * NN * DQ;
    const __half* Kg = g_kf + (size_t)bh * NN * DQ;
    const __half* Vg = g_vtf + (size_t)bh * NN * DD;  // [d][n]

    // ---- Stage Q (128 x 80) ----
#pragma unroll
    for (int it = 0; it < 8; it++) {       // cols 0..63: 1024 chunks
        const int c = tid + 128 * it;
        const int row = c >> 3, col = c & 7;
        cpa16(s2u(&Qs[row * QSTR + col * 8]), &Qg[(size_t)(q0 + row) * DQ + col * 8]);
    }
    {                                      // cols 64..79: 256 chunks
#pragma unroll
        for (int it = 0; it < 2; it++) {
            const int c = tid + 128 * it;
            const int row = c >> 1, col = 8 + (c & 1);
            cpa16(s2u(&Qs[row * QSTR + col * 8]), &Qg[(size_t)(q0 + row) * DQ + col * 8]);
        }
    }
    CP_COMMIT();
    CP_WAIT0();
    __syncthreads();

    uint32_t qf[2][5][4];
#pragma unroll
    for (int g = 0; g < 2; g++)
#pragma unroll
        for (int s = 0; s < 5; s++) {
            const int off = (warp * 32 + g * 16 + (lane & 15)) * QSTR + s * 16 + (lane >> 4) * 8;
            ldsm_x4(qf[g][s], s2u(&Qs[off]));
        }

    auto load_kv = [&](int s, int k0) {
        __half* kb = kvs + s * F_STAGE;
        __half* vb = kb + F_K_ELE;
#pragma unroll
        for (int it = 0; it < 4; it++) {   // K cols 0..63 (512) + V (512)
            const int c = tid + 128 * it;
            const int row = c >> 3, col = c & 7;
            cpa16(s2u(&kb[row * QSTR + col * 8]), &Kg[(size_t)(k0 + row) * DQ + col * 8]);
            cpa16(s2u(&vb[row * VSTR + col * 8]), &Vg[(size_t)row * NN + k0 + col * 8]);
        }
        {                                  // K cols 64..79: 128 chunks
            const int row = tid >> 1, col = 8 + (tid & 1);
            cpa16(s2u(&kb[row * QSTR + col * 8]), &Kg[(size_t)(k0 + row) * DQ + col * 8]);
        }
        CP_COMMIT();
    };

    float oacc[2][8][4];
#pragma unroll
    for (int g = 0; g < 2; g++)
#pragma unroll
        for (int u = 0; u < 8; u++)
#pragma unroll
            for (int r = 0; r < 4; r++) oacc[g][u][r] = 0.0f;
    float lacc[2][4];
#pragma unroll
    for (int g = 0; g < 2; g++)
#pragma unroll
        for (int r = 0; r < 4; r++) lacc[g][r] = 0.0f;

    const uint32_t ONES2 = 0x3C003C00u;
    uint32_t onesb[2] = {ONES2, ONES2};

    constexpr int NKT = NN / 64;  // 36
    load_kv(0, 0);
    load_kv(1, 64);
    for (int kt = 0; kt < NKT; kt++) {
        if (kt + 2 < NKT)      { load_kv((kt + 2) % 3, (kt + 2) * 64); CP_WAIT2(); }
        else if (kt + 1 < NKT) { CP_WAIT1(); }
        else                   { CP_WAIT0(); }
        __syncthreads();
        const __half* sK = kvs + (kt % 3) * F_STAGE;
        const __half* sV = sK + F_K_ELE;

        // S' - M0 = Q' @ K'^T
        float sfr[2][8][4];
#pragma unroll
        for (int g = 0; g < 2; g++)
#pragma unroll
            for (int t = 0; t < 8; t++)
#pragma unroll
                for (int r = 0; r < 4; r++) sfr[g][t][r] = 0.0f;
#pragma unroll
        for (int t = 0; t < 8; t++) {
            const int base = (8 * t + (lane & 7)) * QSTR + (lane >> 3) * 8;
            const int base2 = (8 * t + (lane & 7)) * QSTR + 64 + ((lane >> 3) & 1) * 8;
            uint32_t k01[4], k23[4], k4[2];
            ldsm_x4(k01, s2u(&sK[base]));
            ldsm_x4(k23, s2u(&sK[base + 32]));
            ldsm_x2(k4,  s2u(&sK[base2]));
#pragma unroll
            for (int g = 0; g < 2; g++) {
                mma16816h(sfr[g][t], qf[g][0], &k01[0]);
                mma16816h(sfr[g][t], qf[g][1], &k01[2]);
                mma16816h(sfr[g][t], qf[g][2], &k23[0]);
                mma16816h(sfr[g][t], qf[g][3], &k23[2]);
                mma16816h(sfr[g][t], qf[g][4], k4);
            }
        }

        // softmax via ex2.approx.f16x2; row sums via ones-MMA
        uint32_t pf[2][4][4];
#pragma unroll
        for (int g = 0; g < 2; g++) {
#pragma unroll
            for (int s = 0; s < 4; s++) {
                pf[g][s][0] = exp2_f16x2(sfr[g][2 * s][0],     sfr[g][2 * s][1]);
                pf[g][s][1] = exp2_f16x2(sfr[g][2 * s][2],     sfr[g][2 * s][3]);
                pf[g][s][2] = exp2_f16x2(sfr[g][2 * s + 1][0], sfr[g][2 * s + 1][1]);
                pf[g][s][3] = exp2_f16x2(sfr[g][2 * s + 1][2], sfr[g][2 * s + 1][3]);
                mma16816h(lacc[g], pf[g][s], onesb);
            }
        }

        // O += P @ V
#pragma unroll
        for (int u = 0; u < 8; u++) {
            const int base = (8 * u + (lane & 7)) * VSTR + (lane >> 3) * 8;
            uint32_t v0f[4], v1f[4];
            ldsm_x4(v0f, s2u(&sV[base]));
            ldsm_x4(v1f, s2u(&sV[base + 32]));
#pragma unroll
            for (int g = 0; g < 2; g++) {
                mma16816h(oacc[g][u], pf[g][0], &v0f[0]);
                mma16816h(oacc[g][u], pf[g][1], &v0f[2]);
                mma16816h(oacc[g][u], pf[g][2], &v1f[0]);
                mma16816h(oacc[g][u], pf[g][3], &v1f[2]);
            }
        }
        __syncthreads();
    }

    // epilogue: normalize by MMA row sums, write att fp16 [b][n][C]
#pragma unroll
    for (int g = 0; g < 2; g++) {
        const float invA = 1.0f / lacc[g][0], invB = 1.0f / lacc[g][2];
        const int qA = q0 + warp * 32 + g * 16 + (lane >> 2);
        const size_t baseA = ((size_t)(b * NN + qA)) * CC + h * DD;
        const size_t baseB = ((size_t)(b * NN + qA + 8)) * CC + h * DD;
#pragma unroll
        for (int u = 0; u < 8; u++) {
            const int c = 8 * u + 2 * (lane & 3);
            *(uint32_t*)&g_atf[baseA + c] =
                pack2h(__float2half_rn(oacc[g][u][0] * invA),
                       __float2half_rn(oacc[g][u][1] * invA));
            *(uint32_t*)&g_atf[baseB + c] =
                pack2h(__float2half_rn(oacc[g][u][2] * invB),
                       __float2half_rn(oacc[g][u][3] * invB));
        }
    }
}

// ---------------------------------------------------------------------------
extern "C" void kernel_launch(void* const* d_in, const int* in_sizes, int n_in,
                              void* d_out, int out_size) {
    const float* x      = (const float*)d_in[0];
    const float* qkv_w  = (const float*)d_in[1];
    const float* proj_w = (const float*)d_in[2];
    const float* proj_b = (const float*)d_in[3];
    const float* temp   = (const float*)d_in[4];
    const float* lw     = (const float*)d_in[5];
    float* out = (float*)d_out;

    cudaFuncSetAttribute(mma_gemm<0>, cudaFuncAttributeMaxDynamicSharedMemorySize, G_SMEM);
    cudaFuncSetAttribute(mma_gemm<1>, cudaFuncAttributeMaxDynamicSharedMemorySize, G_SMEM);
    cudaFuncSetAttribute(flash_mma,   cudaFuncAttributeMaxDynamicSharedMemorySize, F_SMEM);

    const int prep_blocks = (int)((SX + SQW + SPW) / 4 / 256);
    prep_cvt<<<prep_blocks, 256>>>(x, qkv_w, proj_w);

    mma_gemm<0><<<dim3(M_TOT / 128, 1536 / 128), 256, G_SMEM>>>(nullptr, temp, nullptr);

    aug_fill<<<(BB * HH * NN + 255) / 256, 256>>>(lw);

    flash_mma<<<dim3(NN / 128, BB * HH), 128, F_SMEM>>>();

    mma_gemm<1><<<dim3(M_TOT / 128, CC / 128), 256, G_SMEM>>>(proj_b, nullptr, out);
}

// round 13
// speedup vs baseline: 2.9591x; 1.0641x over previous
#include <cuda_runtime.h>
#include <cuda_bf16.h>
#include <cuda_fp16.h>
#include <stdint.h>

// LocalitySelfAttention: B=8, N=2304 (48x48), C=512, H=8, D=64.
// All-fp16 tensor pipeline (fp32 accumulate).
// Locality bias + temperature + softmax shift folded into augmented QK^T (D 64->72,
// aug chunk via m16n8k8). ex2.approx.f16x2 softmax; row-sums via ones-MMA.
// Single-barrier software pipelines everywhere.

constexpr int BB = 8;
constexpr int NN = 2304;
constexpr int CC = 512;
constexpr int HH = 8;
constexpr int DD = 64;
constexpr int DQ = 72;                   // augmented head dim (64 + 8)
constexpr int GG = 48;
constexpr int M_TOT = BB * NN;
constexpr size_t SX  = (size_t)M_TOT * CC;
constexpr size_t SQK = (size_t)BB * HH * NN * DQ;
constexpr size_t SQW = (size_t)1536 * 512;
constexpr size_t SPW = (size_t)512 * 512;
constexpr float LOG2E = 1.4426950408889634f;
constexpr float M0 = 8.0f;

__device__ __half g_xf[SX];
__device__ __half g_wqf[SQW];
__device__ __half g_wpf[SPW];
__device__ __half g_qf[SQK];         // [bh][n][72]
__device__ __half g_kf[SQK];         // [bh][n][72]
__device__ __half g_vtf[SX];         // [bh][d][n]
__device__ __half g_atf[SX];         // [b][n][C]

__device__ __forceinline__ uint32_t pack2h(__half a, __half b) {
    __half2 t; t.x = a; t.y = b;
    return *reinterpret_cast<uint32_t*>(&t);
}
__device__ __forceinline__ void mma16816h(float* c, const uint32_t* a, const uint32_t* b) {
    asm volatile(
        "mma.sync.aligned.m16n8k16.row.col.f32.f16.f16.f32 "
        "{%0,%1,%2,%3}, {%4,%5,%6,%7}, {%8,%9}, {%0,%1,%2,%3};"
        : "+f"(c[0]), "+f"(c[1]), "+f"(c[2]), "+f"(c[3])
        : "r"(a[0]), "r"(a[1]), "r"(a[2]), "r"(a[3]), "r"(b[0]), "r"(b[1]));
}
__device__ __forceinline__ void mma16808h(float* c, const uint32_t* a, uint32_t b) {
    asm volatile(
        "mma.sync.aligned.m16n8k8.row.col.f32.f16.f16.f32 "
        "{%0,%1,%2,%3}, {%4,%5}, {%6}, {%0,%1,%2,%3};"
        : "+f"(c[0]), "+f"(c[1]), "+f"(c[2]), "+f"(c[3])
        : "r"(a[0]), "r"(a[1]), "r"(b));
}
__device__ __forceinline__ void ldsm_x4(uint32_t* r, uint32_t addr) {
    asm volatile("ldmatrix.sync.aligned.m8n8.x4.shared.b16 {%0,%1,%2,%3}, [%4];"
        : "=r"(r[0]), "=r"(r[1]), "=r"(r[2]), "=r"(r[3]) : "r"(addr));
}
__device__ __forceinline__ void ldsm_x2(uint32_t* r, uint32_t addr) {
    asm volatile("ldmatrix.sync.aligned.m8n8.x2.shared.b16 {%0,%1}, [%2];"
        : "=r"(r[0]), "=r"(r[1]) : "r"(addr));
}
__device__ __forceinline__ void ldsm_x1(uint32_t* r, uint32_t addr) {
    asm volatile("ldmatrix.sync.aligned.m8n8.x1.shared.b16 {%0}, [%1];"
        : "=r"(r[0]) : "r"(addr));
}
__device__ __forceinline__ uint32_t s2u(const void* p) {
    return (uint32_t)__cvta_generic_to_shared(p);
}
__device__ __forceinline__ void cpa16(uint32_t s, const void* g) {
    asm volatile("cp.async.ca.shared.global [%0], [%1], 16;" :: "r"(s), "l"(g));
}
__device__ __forceinline__ uint32_t exp2_f16x2(float lo, float hi) {
    uint32_t c, e;
    asm("cvt.rn.f16x2.f32 %0, %1, %2;" : "=r"(c) : "f"(hi), "f"(lo));
    asm("ex2.approx.f16x2 %0, %1;" : "=r"(e) : "r"(c));
    return e;
}
#define CP_COMMIT() asm volatile("cp.async.commit_group;")
#define CP_WAIT0()  asm volatile("cp.async.wait_group 0;")
#define CP_WAIT1()  asm volatile("cp.async.wait_group 1;")

// ---------------------------------------------------------------------------
// Prep: fp32 -> fp16, 8 elems/thread.
// ---------------------------------------------------------------------------
__global__ __launch_bounds__(256)
void prep_cvt(const float* __restrict__ x, const float* __restrict__ wq,
              const float* __restrict__ wp) {
    const size_t i8 = ((size_t)blockIdx.x * 256 + threadIdx.x) * 8;
    const float* src; __half* dst; size_t off;
    if (i8 < SX)                  { src = x;  dst = g_xf;  off = i8; }
    else if (i8 < SX + SQW)       { src = wq; dst = g_wqf; off = i8 - SX; }
    else if (i8 < SX + SQW + SPW) { src = wp; dst = g_wpf; off = i8 - SX - SQW; }
    else return;
    const float4 v0 = *(const float4*)(src + off);
    const float4 v1 = *(const float4*)(src + off + 4);
    uint32_t r[4];
    r[0] = pack2h(__float2half_rn(v0.x), __float2half_rn(v0.y));
    r[1] = pack2h(__float2half_rn(v0.z), __float2half_rn(v0.w));
    r[2] = pack2h(__float2half_rn(v1.x), __float2half_rn(v1.y));
    r[3] = pack2h(__float2half_rn(v1.z), __float2half_rn(v1.w));
    *(uint4*)&dst[off] = *(uint4*)r;
}

// ---------------------------------------------------------------------------
// Aug fill: 8 augmentation columns of q and k per (bh, n).
// q: [fy/8, fx/8, -1/8, -M0, 0,0,0,0]   k: [16w*fy, 16w*fx, 8w*kz, 1, 0,0,0,0]
// ---------------------------------------------------------------------------
__global__ __launch_bounds__(256)
void aug_fill(const float* __restrict__ lw) {
    const int idx = blockIdx.x * 256 + threadIdx.x;
    if (idx >= BB * HH * NN) return;
    const int bh = idx / NN, n = idx - bh * NN;
    const int h = bh & 7;
    const int y = n / GG, x = n - y * GG;
    const float wb2 = lw[h] * (LOG2E / 4418.0f);
    const float fy = (float)y, fx = (float)x;

    uint32_t qa[4], ka[4];
    qa[0] = pack2h(__float2half_rn(fy * 0.125f), __float2half_rn(fx * 0.125f));
    qa[1] = pack2h(__float2half_rn(-0.125f), __float2half_rn(-M0));
    qa[2] = 0u; qa[3] = 0u;
    ka[0] = pack2h(__float2half_rn(16.0f * wb2 * fy), __float2half_rn(16.0f * wb2 * fx));
    ka[1] = pack2h(__float2half_rn(8.0f * wb2 * (fy * fy + fx * fx)), __float2half_rn(1.0f));
    ka[2] = 0u; ka[3] = 0u;

    *(uint4*)(g_qf + ((size_t)bh * NN + n) * DQ + 64) = *(uint4*)qa;
    *(uint4*)(g_kf + ((size_t)bh * NN + n) * DQ + 64) = *(uint4*)ka;
}

// ---------------------------------------------------------------------------
// GEMM fp16: block 128x128, k-chunk 32, 8 warps (2m x 4n), 3-stage pipe,
// one barrier per iteration.
// ---------------------------------------------------------------------------
constexpr int GSTR = 40;
constexpr int G_TILE = 128 * GSTR;
constexpr int G_STAGE = 2 * G_TILE;
constexpr int G_SMEM = 3 * G_STAGE * 2;

template <int MODE>
__global__ __launch_bounds__(256, 2)
void mma_gemm(const float* __restrict__ bias, const float* __restrict__ temp,
              float* __restrict__ out) {
    extern __shared__ __half smem[];

    const __half* A = (MODE == 0) ? g_xf : g_atf;
    const __half* B = (MODE == 0) ? g_wqf : g_wpf;

    const int tid = threadIdx.x;
    const int lane = tid & 31, warp = tid >> 5;
    const int wm = warp >> 2, wn = warp & 3;
    const int bm = blockIdx.x * 128, bn = blockIdx.y * 128;

    auto load_stage = [&](int s, int k0) {
        __half* base = smem + s * G_STAGE;
#pragma unroll
        for (int it = 0; it < 2; it++) {
            const int c = tid + 256 * it;
            const int row = c >> 2, col = c & 3;
            const size_t ga = (size_t)(bm + row) * CC + k0 + col * 8;
            const size_t gb = (size_t)(bn + row) * CC + k0 + col * 8;
            const int so = row * GSTR + col * 8;
            cpa16(s2u(base + so), &A[ga]);
            cpa16(s2u(base + G_TILE + so), &B[gb]);
        }
        CP_COMMIT();
    };

    float acc[4][4][4];
#pragma unroll
    for (int i = 0; i < 4; i++)
#pragma unroll
        for (int j = 0; j < 4; j++)
#pragma unroll
            for (int r = 0; r < 4; r++) acc[i][j][r] = 0.0f;

    constexpr int NIT = CC / 32;
    load_stage(0, 0);
    load_stage(1, 32);
    for (int i = 0; i < NIT; i++) {
        if (i + 1 < NIT) { CP_WAIT1(); } else { CP_WAIT0(); }
        __syncthreads();
        if (i + 2 < NIT) load_stage((i + 2) % 3, (i + 2) * 32);
        const __half* sA = smem + (i % 3) * G_STAGE;
        const __half* sB = sA + G_TILE;

        uint32_t bf[4][4];
#pragma unroll
        for (int nt = 0; nt < 4; nt++) {
            const int boff = (wn * 32 + nt * 8 + (lane & 7)) * GSTR + (lane >> 3) * 8;
            ldsm_x4(bf[nt], s2u(&sB[boff]));
        }
#pragma unroll
        for (int mt = 0; mt < 4; mt++) {
            uint32_t af[2][4];
#pragma unroll
            for (int s = 0; s < 2; s++) {
                const int aoff = (wm * 64 + mt * 16 + (lane & 15)) * GSTR + s * 16 + (lane >> 4) * 8;
                ldsm_x4(af[s], s2u(&sA[aoff]));
            }
#pragma unroll
            for (int s = 0; s < 2; s++)
#pragma unroll
                for (int nt = 0; nt < 4; nt++)
                    mma16816h(acc[mt][nt], af[s], &bf[nt][2 * s]);
        }
    }

#pragma unroll
    for (int mt = 0; mt < 4; mt++) {
#pragma unroll
        for (int nt = 0; nt < 4; nt++) {
            const int rA = bm + wm * 64 + mt * 16 + (lane >> 2);
            const int rB = rA + 8;
            const int o = bn + wn * 32 + nt * 8 + 2 * (lane & 3);
            if (MODE == 0) {
                const int part = o >> 9, h = (o >> 6) & 7, d = o & 63;
                const int bA = rA / NN, nA = rA - bA * NN;
                const int bB = rB / NN, nB = rB - bB * NN;
                const int bhA = bA * HH + h, bhB = bB * HH + h;
                float sc = 1.0f;
                if (part == 0) sc = __expf(temp[h]) * LOG2E;
                const __half f0 = __float2half_rn(acc[mt][nt][0] * sc);
                const __half f1 = __float2half_rn(acc[mt][nt][1] * sc);
                const __half f2 = __float2half_rn(acc[mt][nt][2] * sc);
                const __half f3 = __float2half_rn(acc[mt][nt][3] * sc);
                if (part == 2) {
                    const size_t iA = ((size_t)bhA * DD + d) * NN + nA;
                    const size_t iB = ((size_t)bhB * DD + d) * NN + nB;
                    g_vtf[iA] = f0; g_vtf[iA + NN] = f1;
                    g_vtf[iB] = f2; g_vtf[iB + NN] = f3;
                } else {
                    __half* dst = (part == 0) ? g_qf : g_kf;
                    const size_t iA = ((size_t)bhA * NN + nA) * DQ + d;
                    const size_t iB = ((size_t)bhB * NN + nB) * DQ + d;
                    *(uint32_t*)&dst[iA] = pack2h(f0, f1);
                    *(uint32_t*)&dst[iB] = pack2h(f2, f3);
                }
            } else {
                const float b0 = bias[o], b1 = bias[o + 1];
                *(float2*)&out[(size_t)rA * CC + o] =
                    make_float2(acc[mt][nt][0] + b0, acc[mt][nt][1] + b1);
                *(float2*)&out[(size_t)rB * CC + o] =
                    make_float2(acc[mt][nt][2] + b0, acc[mt][nt][3] + b1);
            }
        }
    }
}

// ---------------------------------------------------------------------------
// Flash attention, fp16, augmented D=72 QK^T (aug via m16n8k8),
// ex2.approx.f16x2 softmax, row sums via ones-MMA. CTA = 128 q x one (b,h),
// 4 warps x 32q. 3-stage pipe, one barrier per iteration.
// ---------------------------------------------------------------------------
constexpr int QSTR = 88;                 // 176B rows (odd 16B mult, LDSM clean)
constexpr int VSTR = 72;
constexpr int FQ_ELE = 128 * QSTR;
constexpr int F_K_ELE = 64 * QSTR;
constexpr int F_V_ELE = 64 * VSTR;
constexpr int F_STAGE = F_K_ELE + F_V_ELE;
constexpr int F_SMEM = (FQ_ELE + 3 * F_STAGE) * 2;  // 83968 B

__global__ __launch_bounds__(128, 2)
void flash_mma() {
    extern __shared__ __half hmem[];
    __half* Qs  = hmem;
    __half* kvs = hmem + FQ_ELE;

    const int tid = threadIdx.x;
    const int lane = tid & 31, warp = tid >> 5;
    const int q0 = blockIdx.x * 128;
    const int bh = blockIdx.y;
    const int b = bh >> 3, h = bh & 7;

    const __half* Qg = g_qf + (size_t)bh * NN * DQ;
    const __half* Kg = g_kf + (size_t)bh * NN * DQ;
    const __half* Vg = g_vtf + (size_t)bh * NN * DD;  // [d][n]

    // ---- Stage Q (128 x 72) ----
#pragma unroll
    for (int it = 0; it < 8; it++) {       // cols 0..63
        const int c = tid + 128 * it;
        const int row = c >> 3, col = c & 7;
        cpa16(s2u(&Qs[row * QSTR + col * 8]), &Qg[(size_t)(q0 + row) * DQ + col * 8]);
    }
    {                                      // cols 64..71: 128 chunks
        cpa16(s2u(&Qs[tid * QSTR + 64]), &Qg[(size_t)(q0 + tid) * DQ + 64]);
    }
    CP_COMMIT();
    CP_WAIT0();
    __syncthreads();

    uint32_t qf[2][4][4], qfa[2][2];
#pragma unroll
    for (int g = 0; g < 2; g++) {
#pragma unroll
        for (int s = 0; s < 4; s++) {
            const int off = (warp * 32 + g * 16 + (lane & 15)) * QSTR + s * 16 + (lane >> 4) * 8;
            ldsm_x4(qf[g][s], s2u(&Qs[off]));
        }
        const int offa = (warp * 32 + g * 16 + (lane & 15)) * QSTR + 64;
        ldsm_x2(qfa[g], s2u(&Qs[offa]));
    }

    auto load_kv = [&](int s, int k0) {
        __half* kb = kvs + s * F_STAGE;
        __half* vb = kb + F_K_ELE;
#pragma unroll
        for (int it = 0; it < 4; it++) {   // K cols 0..63 + V
            const int c = tid + 128 * it;
            const int row = c >> 3, col = c & 7;
            cpa16(s2u(&kb[row * QSTR + col * 8]), &Kg[(size_t)(k0 + row) * DQ + col * 8]);
            cpa16(s2u(&vb[row * VSTR + col * 8]), &Vg[(size_t)row * NN + k0 + col * 8]);
        }
        if (tid < 64) {                    // K cols 64..71: 64 chunks
            cpa16(s2u(&kb[tid * QSTR + 64]), &Kg[(size_t)(k0 + tid) * DQ + 64]);
        }
        CP_COMMIT();
    };

    float oacc[2][8][4];
#pragma unroll
    for (int g = 0; g < 2; g++)
#pragma unroll
        for (int u = 0; u < 8; u++)
#pragma unroll
            for (int r = 0; r < 4; r++) oacc[g][u][r] = 0.0f;
    float lacc[2][4];
#pragma unroll
    for (int g = 0; g < 2; g++)
#pragma unroll
        for (int r = 0; r < 4; r++) lacc[g][r] = 0.0f;

    const uint32_t ONES2 = 0x3C003C00u;
    uint32_t onesb[2] = {ONES2, ONES2};

    constexpr int NKT = NN / 64;  // 36
    load_kv(0, 0);
    load_kv(1, 64);
    for (int kt = 0; kt < NKT; kt++) {
        if (kt + 1 < NKT) { CP_WAIT1(); } else { CP_WAIT0(); }
        __syncthreads();
        if (kt + 2 < NKT) load_kv((kt + 2) % 3, (kt + 2) * 64);
        const __half* sK = kvs + (kt % 3) * F_STAGE;
        const __half* sV = sK + F_K_ELE;

        // S' - M0 = Q' @ K'^T (aug chunk via m16n8k8)
        float sfr[2][8][4];
#pragma unroll
        for (int g = 0; g < 2; g++)
#pragma unroll
            for (int t = 0; t < 8; t++)
#pragma unroll
                for (int r = 0; r < 4; r++) sfr[g][t][r] = 0.0f;
#pragma unroll
        for (int t = 0; t < 8; t++) {
            const int base = (8 * t + (lane & 7)) * QSTR + (lane >> 3) * 8;
            uint32_t k01[4], k23[4], k4[1];
            ldsm_x4(k01, s2u(&sK[base]));
            ldsm_x4(k23, s2u(&sK[base + 32]));
            ldsm_x1(k4,  s2u(&sK[(8 * t + (lane & 7)) * QSTR + 64]));
#pragma unroll
            for (int g = 0; g < 2; g++) {
                mma16816h(sfr[g][t], qf[g][0], &k01[0]);
                mma16816h(sfr[g][t], qf[g][1], &k01[2]);
                mma16816h(sfr[g][t], qf[g][2], &k23[0]);
                mma16816h(sfr[g][t], qf[g][3], &k23[2]);
                mma16808h(sfr[g][t], qfa[g], k4[0]);
            }
        }

        // softmax via ex2.approx.f16x2; row sums via ones-MMA
        uint32_t pf[2][4][4];
#pragma unroll
        for (int g = 0; g < 2; g++) {
#pragma unroll
            for (int s = 0; s < 4; s++) {
                pf[g][s][0] = exp2_f16x2(sfr[g][2 * s][0],     sfr[g][2 * s][1]);
                pf[g][s][1] = exp2_f16x2(sfr[g][2 * s][2],     sfr[g][2 * s][3]);
                pf[g][s][2] = exp2_f16x2(sfr[g][2 * s + 1][0], sfr[g][2 * s + 1][1]);
                pf[g][s][3] = exp2_f16x2(sfr[g][2 * s + 1][2], sfr[g][2 * s + 1][3]);
                mma16816h(lacc[g], pf[g][s], onesb);
            }
        }

        // O += P @ V
#pragma unroll
        for (int u = 0; u < 8; u++) {
            const int base = (8 * u + (lane & 7)) * VSTR + (lane >> 3) * 8;
            uint32_t v0f[4], v1f[4];
            ldsm_x4(v0f, s2u(&sV[base]));
            ldsm_x4(v1f, s2u(&sV[base + 32]));
#pragma unroll
            for (int g = 0; g < 2; g++) {
                mma16816h(oacc[g][u], pf[g][0], &v0f[0]);
                mma16816h(oacc[g][u], pf[g][1], &v0f[2]);
                mma16816h(oacc[g][u], pf[g][2], &v1f[0]);
                mma16816h(oacc[g][u], pf[g][3], &v1f[2]);
            }
        }
    }

    // epilogue: normalize by MMA row sums, write att fp16 [b][n][C]
#pragma unroll
    for (int g = 0; g < 2; g++) {
        const float invA = 1.0f / lacc[g][0], invB = 1.0f / lacc[g][2];
        const int qA = q0 + warp * 32 + g * 16 + (lane >> 2);
        const size_t baseA = ((size_t)(b * NN + qA)) * CC + h * DD;
        const size_t baseB = ((size_t)(b * NN + qA + 8)) * CC + h * DD;
#pragma unroll
        for (int u = 0; u < 8; u++) {
            const int c = 8 * u + 2 * (lane & 3);
            *(uint32_t*)&g_atf[baseA + c] =
                pack2h(__float2half_rn(oacc[g][u][0] * invA),
                       __float2half_rn(oacc[g][u][1] * invA));
            *(uint32_t*)&g_atf[baseB + c] =
                pack2h(__float2half_rn(oacc[g][u][2] * invB),
                       __float2half_rn(oacc[g][u][3] * invB));
        }
    }
}

// ---------------------------------------------------------------------------
extern "C" void kernel_launch(void* const* d_in, const int* in_sizes, int n_in,
                              void* d_out, int out_size) {
    const float* x      = (const float*)d_in[0];
    const float* qkv_w  = (const float*)d_in[1];
    const float* proj_w = (const float*)d_in[2];
    const float* proj_b = (const float*)d_in[3];
    const float* temp   = (const float*)d_in[4];
    const float* lw     = (const float*)d_in[5];
    float* out = (float*)d_out;

    cudaFuncSetAttribute(mma_gemm<0>, cudaFuncAttributeMaxDynamicSharedMemorySize, G_SMEM);
    cudaFuncSetAttribute(mma_gemm<1>, cudaFuncAttributeMaxDynamicSharedMemorySize, G_SMEM);
    cudaFuncSetAttribute(flash_mma,   cudaFuncAttributeMaxDynamicSharedMemorySize, F_SMEM);

    const int prep_blocks = (int)((SX + SQW + SPW) / 8 / 256);
    prep_cvt<<<prep_blocks, 256>>>(x, qkv_w, proj_w);

    mma_gemm<0><<<dim3(M_TOT / 128, 1536 / 128), 256, G_SMEM>>>(nullptr, temp, nullptr);

    aug_fill<<<(BB * HH * NN + 255) / 256, 256>>>(lw);

    flash_mma<<<dim3(NN / 128, BB * HH), 128, F_SMEM>>>();

    mma_gemm<1><<<dim3(M_TOT / 128, CC / 128), 256, G_SMEM>>>(proj_b, nullptr, out);
}